// round 12
// baseline (speedup 1.0000x reference)
#include <cuda_runtime.h>
#include <cuda_fp16.h>
#include <math.h>
#include <stdint.h>

// Shapes (fixed for this problem)
#define NN   4096
#define NV   3
#define MM   16
#define EE   256
#define HH   8
#define DD   32
#define NR   (NN*NV)
#define SQRT_E 16.0f
#define SCALING 0.17677669529663687f   // 32^-0.5

// ---------------- scratch (device globals; no allocation allowed) -------------
__device__ float d_g_src[NR*EE];                       // fp32 (gram input, gout residual)
__device__ __align__(16) uint32_t d_gsh[NR*128];       // g_src fp16 [row][128 w]
__device__ float d_hsrc[NN*EE];                        // h_src fp32 (ng residual)
__device__ __align__(16) uint32_t d_h2h[NN*256];       // h2 hi [node][256 w]
__device__ __align__(16) uint32_t d_h2l[NN*256];
__device__ __align__(16) uint32_t d_gramh[NN*512];
__device__ __align__(16) uint32_t d_graml[NN*512];
__device__ __align__(16) uint32_t d_t1h[NN*256];
__device__ __align__(16) uint32_t d_t1l[NN*256];
__device__ __align__(16) uint32_t d_qh[NN*128];
__device__ __align__(16) uint32_t d_ql[NN*128];
__device__ __align__(16) uint32_t d_kh[NN*128];
__device__ __align__(16) uint32_t d_kl[NN*128];
__device__ __align__(16) uint32_t d_v16[NN*128];
__device__ __align__(16) uint32_t d_vg16[NR*128];
__device__ __align__(16) __half  d_vt[HH*128*NN];      // combined V transposed [h][c][node]
__device__ __align__(16) uint32_t d_outv16[NN*128];
__device__ __align__(16) uint32_t d_outg16[NR*128];
__device__ __align__(16) uint32_t d_hnew16[NN*128];
__device__ float d_gnew[NR*EE];
// packed weights (transposed [n][k/2 words])
__device__ __align__(16) uint32_t d_wg1h[512*512], d_wg1l[512*512];
__device__ __align__(16) uint32_t d_wg2h[256*256], d_wg2l[256*256];
__device__ __align__(16) uint32_t d_wqh[256*256],  d_wql[256*256];
__device__ __align__(16) uint32_t d_wkh[256*256],  d_wkl[256*256];
__device__ __align__(16) uint32_t d_wvh[256*256];
__device__ __align__(16) uint32_t d_wvgh[256*128];
__device__ __align__(16) uint32_t d_wngh[256*128];
__device__ __align__(16) uint32_t d_wgouth[256*128];
__device__ __align__(16) uint32_t d_whdech[256*128];

// ---------------- helpers ------------------------------------------------------
__device__ __forceinline__ uint32_t packh2(__half a, __half b) {
    __half2 t = __halves2half2(a, b);
    return *reinterpret_cast<uint32_t*>(&t);
}
__device__ __forceinline__ uint32_t cvth(float a, float b) {
    __half2 t = __floats2half2_rn(a, b);
    return *reinterpret_cast<uint32_t*>(&t);
}
__device__ __forceinline__ void cvthl(float a, float b, uint32_t& hi, uint32_t& lo) {
    __half ha = __float2half_rn(a), hb = __float2half_rn(b);
    __half la = __float2half_rn(a - __half2float(ha));
    __half lb = __float2half_rn(b - __half2float(hb));
    hi = packh2(ha, hb);
    lo = packh2(la, lb);
}

__device__ __forceinline__ void mma_f16(float c[4],
    uint32_t a0, uint32_t a1, uint32_t a2, uint32_t a3,
    uint32_t b0, uint32_t b1)
{
    asm volatile(
        "mma.sync.aligned.m16n8k16.row.col.f32.f16.f16.f32 "
        "{%0,%1,%2,%3}, {%4,%5,%6,%7}, {%8,%9}, {%0,%1,%2,%3};\n"
        : "+f"(c[0]), "+f"(c[1]), "+f"(c[2]), "+f"(c[3])
        : "r"(a0), "r"(a1), "r"(a2), "r"(a3), "r"(b0), "r"(b1));
}

__device__ __forceinline__ void ldsm4(uint32_t& r0, uint32_t& r1,
                                      uint32_t& r2, uint32_t& r3, const void* p)
{
    uint32_t addr = (uint32_t)__cvta_generic_to_shared(p);
    asm volatile("ldmatrix.sync.aligned.m8n8.x4.shared.b16 {%0,%1,%2,%3}, [%4];"
                 : "=r"(r0), "=r"(r1), "=r"(r2), "=r"(r3) : "r"(addr));
}

// ---------------- weight pre-pack: W[K][Nn] fp32 -> [n][K/2 words] hi(/lo) -----
template<bool X2>
__global__ void packW(const float* __restrict__ W, uint32_t* __restrict__ Wh,
                      uint32_t* __restrict__ Wl, int kshift, int Nn)
{
    int idx = blockIdx.x * 256 + threadIdx.x;   // over Nn * K/2
    int K2w = 1 << kshift;
    int n = idx >> kshift, w = idx & (K2w - 1);
    float a = W[(2*w)*Nn + n];
    float b = W[(2*w+1)*Nn + n];
    if (X2) cvthl(a, b, Wh[idx], Wl[idx]);
    else    Wh[idx] = cvth(a, b);
}

// ---------------- g_src = (equ @ W_equ) * 16  (+ fp16 copy) --------------------
__global__ void gsrc_kernel(const float* __restrict__ equ,
                            const float* __restrict__ W_equ)
{
    __shared__ float es[MM];
    int r = blockIdx.x;
    int e = threadIdx.x;
    if (e < MM) es[e] = equ[r*MM + e];
    __syncthreads();
    float acc = 0.f;
#pragma unroll
    for (int m = 0; m < MM; m++) acc += es[m] * W_equ[m*EE + e];
    d_g_src[r*EE + e] = acc * SQRT_E;
    ((__half*)d_gsh)[r*EE + e] = __float2half_rn(acc * SQRT_E);
}

// ---------------- h_src = h*16  (fp32 + packed hi/lo into h2 right half) -------
__global__ void hsrc_kernel(const float* __restrict__ h)
{
    int i = blockIdx.x, e = threadIdx.x;
    float v = h[i*EE + e] * SQRT_E;
    d_hsrc[i*EE + e] = v;
    __half hi = __float2half_rn(v);
    __half lo = __float2half_rn(v - __half2float(hi));
    ((__half*)d_h2h)[i*512 + 256 + e] = hi;
    ((__half*)d_h2l)[i*512 + 256 + e] = lo;
}

// ---------------- g2p + Gram (emit packed hi/lo) -------------------------------
__global__ void gram_kernel(const float* __restrict__ W_gproj)
{
    __shared__ float gs[NV][EE];
    __shared__ float g2p[NV][32];
    int node = blockIdx.x;
    int t = threadIdx.x;
#pragma unroll
    for (int i = 0; i < NV; i++) gs[i][t] = d_g_src[(node*NV + i)*EE + t];
    __syncthreads();
    if (t < 96) {
        int i = t >> 5, a = t & 31;
        float acc = 0.f;
#pragma unroll 4
        for (int k2 = 0; k2 < EE; k2++) acc += gs[i][k2] * W_gproj[k2*32 + a];
        g2p[i][a] = acc;
    }
    __syncthreads();
#pragma unroll
    for (int o2 = t; o2 < 512; o2 += 256) {
        int e0 = 2*o2;
        int a = e0 >> 5, b = e0 & 31;
        float v0 = g2p[0][a]*g2p[0][b]   + g2p[1][a]*g2p[1][b]   + g2p[2][a]*g2p[2][b];
        float v1 = g2p[0][a]*g2p[0][b+1] + g2p[1][a]*g2p[1][b+1] + g2p[2][a]*g2p[2][b+1];
        cvthl(v0, v1, d_gramh[node*512 + o2], d_graml[node*512 + o2]);
    }
}

// ---------------- fully-packed fp16 tensor-core GEMM ---------------------------
// A: [M][K/2 words] hi(/lo).  B: [n][K/2 words] hi(/lo) (pre-transposed weights).
// EMIT 0: fp32 C (ldc floats).  EMIT 1: fp16 Ch (ldc words).  EMIT 2: hi/lo.
// 128x64 tile, warp 32x32, K-chunk 32.
template<bool RELU, bool BIAS, bool RES, bool X2, int EMIT>
__global__ __launch_bounds__(256, 2)
void gemm16p(const uint32_t* __restrict__ Ah, const uint32_t* __restrict__ Al,
             const uint32_t* __restrict__ Bh, const uint32_t* __restrict__ Bl,
             const float* __restrict__ bias, const float* __restrict__ resid,
             float* __restrict__ C, uint32_t* __restrict__ Ch, uint32_t* __restrict__ Cl,
             int K, int ldr, int ldc, float alpha)
{
    __shared__ uint32_t Ahi[128][20];
    __shared__ uint32_t Alo[X2 ? 128 : 1][20];
    __shared__ uint32_t Bhi[64][20];
    __shared__ uint32_t Blo[X2 ? 64 : 1][20];

    int tid = threadIdx.x, lane = tid & 31, w = tid >> 5;
    int m0 = blockIdx.y * 128, n0 = blockIdx.x * 64;
    int rw = (w >> 1) * 32;
    int cw = (w & 1) * 32;
    int g  = lane >> 3;
    int K2w = K >> 1;

    int afr = tid >> 1;            // A fill: row 0..127
    int afw = (tid & 1) * 8;       // A fill: word base {0,8}
    int bfr = tid >> 2;            // B fill: row n 0..63
    int bfw = (tid & 3) * 4;       // B fill: word base

    float acc[2][4][4] = {};
    uint4 pah0, pah1, pal0, pal1, pbh, pbl;

    // prologue prefetch (k0w = 0)
    {
        const uint4* ap = (const uint4*)&Ah[(uint64_t)(m0 + afr)*K2w + afw];
        pah0 = ap[0]; pah1 = ap[1];
        pbh  = *(const uint4*)&Bh[(n0 + bfr)*K2w + bfw];
        if (X2) {
            const uint4* alp = (const uint4*)&Al[(uint64_t)(m0 + afr)*K2w + afw];
            pal0 = alp[0]; pal1 = alp[1];
            pbl  = *(const uint4*)&Bl[(n0 + bfr)*K2w + bfw];
        }
    }

    for (int k0w = 0; k0w < K2w; k0w += 16) {
        __syncthreads();
        *(uint4*)&Ahi[afr][afw]     = pah0;
        *(uint4*)&Ahi[afr][afw + 4] = pah1;
        *(uint4*)&Bhi[bfr][bfw]     = pbh;
        if (X2) {
            *(uint4*)&Alo[afr][afw]     = pal0;
            *(uint4*)&Alo[afr][afw + 4] = pal1;
            *(uint4*)&Blo[bfr][bfw]     = pbl;
        }
        __syncthreads();
        if (k0w + 16 < K2w) {
            const uint4* ap = (const uint4*)&Ah[(uint64_t)(m0 + afr)*K2w + k0w + 16 + afw];
            pah0 = ap[0]; pah1 = ap[1];
            pbh  = *(const uint4*)&Bh[(n0 + bfr)*K2w + k0w + 16 + bfw];
            if (X2) {
                const uint4* alp = (const uint4*)&Al[(uint64_t)(m0 + afr)*K2w + k0w + 16 + afw];
                pal0 = alp[0]; pal1 = alp[1];
                pbl  = *(const uint4*)&Bl[(n0 + bfr)*K2w + k0w + 16 + bfw];
            }
        }
#pragma unroll
        for (int kk = 0; kk < 2; kk++) {
            int arow = rw + (g&1)*8 + (lane&7);
            int acol = kk*8 + (g>>1)*4;
            uint32_t ah[2][4], al[2][4];
            ldsm4(ah[0][0],ah[0][1],ah[0][2],ah[0][3], &Ahi[arow][acol]);
            ldsm4(ah[1][0],ah[1][1],ah[1][2],ah[1][3], &Ahi[arow+16][acol]);
            if (X2) {
                ldsm4(al[0][0],al[0][1],al[0][2],al[0][3], &Alo[arow][acol]);
                ldsm4(al[1][0],al[1][1],al[1][2],al[1][3], &Alo[arow+16][acol]);
            }
            uint32_t bh[8], bl[8];
#pragma unroll
            for (int jj = 0; jj < 2; jj++) {
                int brow = cw + jj*16 + (g>>1)*8 + (lane&7);
                int bcol = kk*8 + (g&1)*4;
                ldsm4(bh[jj*4+0],bh[jj*4+1],bh[jj*4+2],bh[jj*4+3], &Bhi[brow][bcol]);
                if (X2)
                    ldsm4(bl[jj*4+0],bl[jj*4+1],bl[jj*4+2],bl[jj*4+3], &Blo[brow][bcol]);
            }
#pragma unroll
            for (int t = 0; t < 2; t++) {
#pragma unroll
                for (int j = 0; j < 4; j++) {
                    uint32_t b0 = bh[(j>>1)*4 + (j&1)*2], b1 = bh[(j>>1)*4 + (j&1)*2 + 1];
                    mma_f16(acc[t][j], ah[t][0],ah[t][1],ah[t][2],ah[t][3], b0, b1);
                    if (X2) {
                        uint32_t c0 = bl[(j>>1)*4 + (j&1)*2], c1 = bl[(j>>1)*4 + (j&1)*2 + 1];
                        mma_f16(acc[t][j], al[t][0],al[t][1],al[t][2],al[t][3], b0, b1);
                        mma_f16(acc[t][j], ah[t][0],ah[t][1],ah[t][2],ah[t][3], c0, c1);
                    }
                }
            }
        }
    }

    // epilogue
#pragma unroll
    for (int t = 0; t < 2; t++) {
        int r0 = m0 + rw + t*16 + (lane >> 2);
#pragma unroll
        for (int j = 0; j < 4; j++) {
            int col = n0 + cw + j*8 + 2*(lane & 3);
            float b0 = 0.f, b1 = 0.f;
            if (BIAS) { b0 = bias[col]; b1 = bias[col+1]; }
#pragma unroll
            for (int h2r = 0; h2r < 2; h2r++) {
                int row = r0 + h2r*8;
                float v0 = acc[t][j][2*h2r+0];
                float v1 = acc[t][j][2*h2r+1];
                if (BIAS) { v0 += b0; v1 += b1; }
                v0 *= alpha; v1 *= alpha;
                if (RES) {
                    v0 += resid[row*ldr + col];
                    v1 += resid[row*ldr + col + 1];
                }
                if (RELU) { v0 = fmaxf(v0, 0.f); v1 = fmaxf(v1, 0.f); }
                if (EMIT == 0) {
                    *(float2*)&C[row*ldc + col] = make_float2(v0, v1);
                } else if (EMIT == 1) {
                    Ch[row*ldc + (col >> 1)] = cvth(v0, v1);
                } else {
                    cvthl(v0, v1, Ch[row*ldc + (col >> 1)], Cl[row*ldc + (col >> 1)]);
                }
            }
        }
    }
}

// ---------------- pack combined V transposed (pure fp16 copy) ------------------
__global__ void pack_v_kernel()
{
    int idx = blockIdx.x * 256 + threadIdx.x;     // over HH*128*NN
    int node = idx & (NN-1);
    int hc = idx >> 12;
    int h = hc >> 7, c = hc & 127;
    __half s;
    if (c < 32) s = ((const __half*)d_v16)[node*256 + h*DD + c];
    else {
        int iv = (c - 32) >> 5, dc = (c - 32) & 31;
        s = ((const __half*)d_vg16)[(node*NV + iv)*256 + h*DD + dc];
    }
    d_vt[idx] = s;
}

// ---------------- register-resident fp16 flash attention -----------------------
#define ATQ 64
#define ATK 64
#define AT2_SMEM_BYTES ((64*20*2 + 128*36)*4)

__global__ __launch_bounds__(128, 3)
void attn_reg_kernel()
{
    extern __shared__ char smc[];
    uint32_t* KH = (uint32_t*)smc;                // [64][20] half2
    uint32_t* KL = KH + 64*20;
    uint32_t* VT = KL + 64*20;                    // [128][36] half2 (n-major, k contig)

    int tid  = threadIdx.x;
    int lane = tid & 31;
    int w    = tid >> 5;
    int g    = lane >> 3;
    int hh   = blockIdx.y;
    int hoff = hh * DD;
    int hw   = hh * 16;          // head word offset
    int qbase = blockIdx.x * ATQ;
    int wbase = w * 16;

    // ---- preload Q fragments (already packed hi/lo) ----
    uint32_t qh[2][4], ql[2][4];
    {
        int gr0 = qbase + wbase + (lane >> 2);
#pragma unroll
        for (int kk = 0; kk < 2; kk++) {
            int w0 = hw + kk*8 + (lane & 3);
            qh[kk][0] = d_qh[gr0*128 + w0];
            qh[kk][1] = d_qh[(gr0+8)*128 + w0];
            qh[kk][2] = d_qh[gr0*128 + w0 + 4];
            qh[kk][3] = d_qh[(gr0+8)*128 + w0 + 4];
            ql[kk][0] = d_ql[gr0*128 + w0];
            ql[kk][1] = d_ql[(gr0+8)*128 + w0];
            ql[kk][2] = d_ql[gr0*128 + w0 + 4];
            ql[kk][3] = d_ql[(gr0+8)*128 + w0 + 4];
        }
    }

    float rmax0 = -1e30f, rmax1 = -1e30f;
    float rsum0 = 0.f, rsum1 = 0.f;
    float acc[16][4] = {};

    for (int kb = 0; kb < NN; kb += ATK) {
        __syncthreads();
#pragma unroll
        for (int l = 0; l < 4; l++) {
            int idx = tid + l*128;
            int row = idx >> 3, cp = (idx & 7) * 2;
            int gg = (kb + row)*128 + hw + cp;
            *(uint2*)&KH[row*20 + cp] = *(const uint2*)&d_kh[gg];
            *(uint2*)&KL[row*20 + cp] = *(const uint2*)&d_kl[gg];
        }
#pragma unroll
        for (int l = 0; l < 8; l++) {
            int idx = tid + l*128;
            int row = idx >> 3;
            int c16 = idx & 7;
            uint4 vv = *(const uint4*)&d_vt[(hh*128 + row)*NN + kb + c16*8];
            *(uint4*)&VT[row*36 + c16*4] = vv;
        }
        __syncthreads();

        // ---- S = Q K^T (fp16 hi/lo) ----
        float sc[8][4];
#pragma unroll
        for (int j = 0; j < 8; j++)
#pragma unroll
            for (int i = 0; i < 4; i++) sc[j][i] = 0.f;
#pragma unroll
        for (int kk = 0; kk < 2; kk++) {
#pragma unroll
            for (int jj = 0; jj < 4; jj++) {
                int nrow = jj*16 + (g>>1)*8 + (lane&7);
                int kc   = kk*8 + (g&1)*4;
                uint32_t bh[4], bl[4];
                ldsm4(bh[0],bh[1],bh[2],bh[3], &KH[nrow*20 + kc]);
                ldsm4(bl[0],bl[1],bl[2],bl[3], &KL[nrow*20 + kc]);
#pragma unroll
                for (int jw = 0; jw < 2; jw++) {
                    int j = 2*jj + jw;
                    uint32_t b0 = bh[jw*2], b1 = bh[jw*2+1];
                    uint32_t c0 = bl[jw*2], c1 = bl[jw*2+1];
                    mma_f16(sc[j], qh[kk][0], qh[kk][1], qh[kk][2], qh[kk][3], b0, b1);
                    mma_f16(sc[j], ql[kk][0], ql[kk][1], ql[kk][2], ql[kk][3], b0, b1);
                    mma_f16(sc[j], qh[kk][0], qh[kk][1], qh[kk][2], qh[kk][3], c0, c1);
                }
            }
        }

        // ---- online softmax in registers; skip rescale if no new max ----
        float m0 = rmax0, m1 = rmax1;
#pragma unroll
        for (int j = 0; j < 8; j++) {
            m0 = fmaxf(m0, fmaxf(sc[j][0], sc[j][1]));
            m1 = fmaxf(m1, fmaxf(sc[j][2], sc[j][3]));
        }
        m0 = fmaxf(m0, __shfl_xor_sync(0xffffffffu, m0, 1));
        m0 = fmaxf(m0, __shfl_xor_sync(0xffffffffu, m0, 2));
        m1 = fmaxf(m1, __shfl_xor_sync(0xffffffffu, m1, 1));
        m1 = fmaxf(m1, __shfl_xor_sync(0xffffffffu, m1, 2));

        bool nm = __any_sync(0xffffffffu, (m0 > rmax0) || (m1 > rmax1));
        if (nm) {
            float alf0 = __expf(rmax0 - m0);
            float alf1 = __expf(rmax1 - m1);
            rsum0 *= alf0; rsum1 *= alf1;
#pragma unroll
            for (int j = 0; j < 16; j++) {
                acc[j][0] *= alf0; acc[j][1] *= alf0;
                acc[j][2] *= alf1; acc[j][3] *= alf1;
            }
            rmax0 = m0; rmax1 = m1;
        }

        uint32_t pp0[8], pp1[8];
        float ps0 = 0.f, ps1 = 0.f;
#pragma unroll
        for (int j = 0; j < 8; j++) {
            float pa = __expf(sc[j][0] - rmax0);
            float pb = __expf(sc[j][1] - rmax0);
            float pc = __expf(sc[j][2] - rmax1);
            float pd = __expf(sc[j][3] - rmax1);
            pp0[j] = cvth(pa, pb);
            pp1[j] = cvth(pc, pd);
            ps0 += pa + pb;
            ps1 += pc + pd;
        }
        ps0 += __shfl_xor_sync(0xffffffffu, ps0, 1);
        ps0 += __shfl_xor_sync(0xffffffffu, ps0, 2);
        ps1 += __shfl_xor_sync(0xffffffffu, ps1, 1);
        ps1 += __shfl_xor_sync(0xffffffffu, ps1, 2);
        rsum0 += ps0;
        rsum1 += ps1;

        // ---- P@V (single fp16) ----
#pragma unroll
        for (int kk = 0; kk < 4; kk++) {
            uint32_t a0 = pp0[2*kk],   a1 = pp1[2*kk];
            uint32_t a2 = pp0[2*kk+1], a3 = pp1[2*kk+1];
#pragma unroll
            for (int jj = 0; jj < 8; jj++) {
                int nrow = jj*16 + (g>>1)*8 + (lane&7);
                int kc   = kk*8 + (g&1)*4;
                uint32_t b[4];
                ldsm4(b[0], b[1], b[2], b[3], &VT[nrow*36 + kc]);
                mma_f16(acc[2*jj],   a0, a1, a2, a3, b[0], b[1]);
                mma_f16(acc[2*jj+1], a0, a1, a2, a3, b[2], b[3]);
            }
        }
    }

    // ---- epilogue: normalize, emit fp16 packed ----
    {
        float inv0 = 1.0f / rsum0;
        float inv1 = 1.0f / rsum1;
        int gr0 = qbase + wbase + (lane >> 2);
        int gr1 = gr0 + 8;
#pragma unroll
        for (int j = 0; j < 16; j++) {
            int col = j*8 + 2*(lane & 3);
            uint32_t w0 = cvth(acc[j][0]*inv0, acc[j][1]*inv0);
            uint32_t w1 = cvth(acc[j][2]*inv1, acc[j][3]*inv1);
            if (col < 32) {
                d_outv16[gr0*128 + ((hoff + col) >> 1)] = w0;
                d_outv16[gr1*128 + ((hoff + col) >> 1)] = w1;
            } else {
                int iv = (col - 32) >> 5, dc = (col - 32) & 31;
                d_outg16[(gr0*NV + iv)*128 + ((hoff + dc) >> 1)] = w0;
                d_outg16[(gr1*NV + iv)*128 + ((hoff + dc) >> 1)] = w1;
            }
        }
    }
}

// ---------------- equ_out = gnew @ W_gdec  ([*,256]@[256,16]) ------------------
__global__ void gdec_kernel(const float* __restrict__ W_gdec, float* __restrict__ out)
{
    __shared__ float gs[16][EE];
    int rbase = blockIdx.x * 16;
    int t = threadIdx.x;
    for (int idx = t; idx < 16*EE; idx += 256)
        gs[idx >> 8][idx & 255] = d_gnew[(rbase + (idx >> 8))*EE + (idx & 255)];
    __syncthreads();
    int lr = t >> 4, c = t & 15;
    float acc = 0.f;
#pragma unroll 4
    for (int k2 = 0; k2 < EE; k2++) acc += gs[lr][k2] * W_gdec[k2*MM + c];
    out[(rbase + lr)*MM + c] = acc;
}

// ------------------------------------------------------------------------------
extern "C" void kernel_launch(void* const* d_in, const int* in_sizes, int n_in,
                              void* d_out, int out_size)
{
    const float* equ    = (const float*)d_in[0];
    const float* h      = (const float*)d_in[1];
    const float* W_equ  = (const float*)d_in[4];
    const float* W_gproj= (const float*)d_in[5];
    const float* W_vg   = (const float*)d_in[6];
    const float* W_g1   = (const float*)d_in[7];
    const float* b_g1   = (const float*)d_in[8];
    const float* W_g2   = (const float*)d_in[9];
    const float* b_g2   = (const float*)d_in[10];
    const float* W_q    = (const float*)d_in[11];
    const float* b_q    = (const float*)d_in[12];
    const float* W_k    = (const float*)d_in[13];
    const float* b_k    = (const float*)d_in[14];
    const float* W_v    = (const float*)d_in[15];
    const float* b_v    = (const float*)d_in[16];
    const float* W_ng   = (const float*)d_in[17];
    const float* b_ng   = (const float*)d_in[18];
    const float* W_gout = (const float*)d_in[19];
    const float* W_gdec = (const float*)d_in[20];
    const float* W_hdec = (const float*)d_in[21];
    const float* b_hdec = (const float*)d_in[22];
    float* out = (float*)d_out;

#define SYM(p, s) void* p; cudaGetSymbolAddress(&p, s)
    SYM(p_gsrc, d_g_src);  SYM(p_gsh, d_gsh);   SYM(p_hsrc, d_hsrc);
    SYM(p_h2h, d_h2h);     SYM(p_h2l, d_h2l);
    SYM(p_gramh, d_gramh); SYM(p_graml, d_graml);
    SYM(p_t1h, d_t1h);     SYM(p_t1l, d_t1l);
    SYM(p_qh, d_qh);       SYM(p_ql, d_ql);
    SYM(p_kh, d_kh);       SYM(p_kl, d_kl);
    SYM(p_v16, d_v16);     SYM(p_vg16, d_vg16);
    SYM(p_outv16, d_outv16); SYM(p_outg16, d_outg16);
    SYM(p_hnew16, d_hnew16); SYM(p_gnew, d_gnew);
    SYM(p_wg1h, d_wg1h); SYM(p_wg1l, d_wg1l);
    SYM(p_wg2h, d_wg2h); SYM(p_wg2l, d_wg2l);
    SYM(p_wqh, d_wqh);   SYM(p_wql, d_wql);
    SYM(p_wkh, d_wkh);   SYM(p_wkl, d_wkl);
    SYM(p_wvh, d_wvh);   SYM(p_wvgh, d_wvgh);
    SYM(p_wngh, d_wngh); SYM(p_wgouth, d_wgouth);
    SYM(p_whdech, d_whdech);
#undef SYM

    // 0) weight pre-pack
    packW<true ><<<512*512/256, 256>>>(W_g1,  (uint32_t*)p_wg1h, (uint32_t*)p_wg1l, 9, 512);
    packW<true ><<<256*256/256, 256>>>(W_g2,  (uint32_t*)p_wg2h, (uint32_t*)p_wg2l, 8, 256);
    packW<true ><<<256*256/256, 256>>>(W_q,   (uint32_t*)p_wqh,  (uint32_t*)p_wql,  8, 256);
    packW<true ><<<256*256/256, 256>>>(W_k,   (uint32_t*)p_wkh,  (uint32_t*)p_wkl,  8, 256);
    packW<false><<<256*256/256, 256>>>(W_v,   (uint32_t*)p_wvh,  nullptr,           8, 256);
    packW<false><<<256*128/256, 256>>>(W_vg,  (uint32_t*)p_wvgh, nullptr,           7, 256);
    packW<false><<<256*128/256, 256>>>(W_ng,  (uint32_t*)p_wngh, nullptr,           7, 256);
    packW<false><<<256*128/256, 256>>>(W_gout,(uint32_t*)p_wgouth,nullptr,          7, 256);
    packW<false><<<256*128/256, 256>>>(W_hdec,(uint32_t*)p_whdech,nullptr,          7, 256);

    // 1) prep
    gsrc_kernel<<<NR, 256>>>(equ, W_equ);
    hsrc_kernel<<<NN, 256>>>(h);
    gram_kernel<<<NN, 256>>>(W_gproj);

    // 2) MLP on gram (X2, emit packed)
    gemm16p<true, true, false, true, 2><<<dim3(8, 32), 256>>>(
        (uint32_t*)p_gramh, (uint32_t*)p_graml, (uint32_t*)p_wg1h, (uint32_t*)p_wg1l,
        b_g1, nullptr, nullptr, (uint32_t*)p_t1h, (uint32_t*)p_t1l, 1024, 0, 256, 1.f);
    gemm16p<false, true, false, true, 2><<<dim3(4, 32), 256>>>(
        (uint32_t*)p_t1h, (uint32_t*)p_t1l, (uint32_t*)p_wg2h, (uint32_t*)p_wg2l,
        b_g2, nullptr, nullptr, (uint32_t*)p_h2h, (uint32_t*)p_h2l, 512, 0, 256, 1.f);

    // 3) q,k (X2 -> packed hi/lo), v,vg (single -> fp16)
    gemm16p<false, true, false, true, 2><<<dim3(4, 32), 256>>>(
        (uint32_t*)p_h2h, (uint32_t*)p_h2l, (uint32_t*)p_wqh, (uint32_t*)p_wql,
        b_q, nullptr, nullptr, (uint32_t*)p_qh, (uint32_t*)p_ql, 512, 0, 128, SCALING);
    gemm16p<false, true, false, true, 2><<<dim3(4, 32), 256>>>(
        (uint32_t*)p_h2h, (uint32_t*)p_h2l, (uint32_t*)p_wkh, (uint32_t*)p_wkl,
        b_k, nullptr, nullptr, (uint32_t*)p_kh, (uint32_t*)p_kl, 512, 0, 128, 1.f);
    gemm16p<false, true, false, false, 1><<<dim3(4, 32), 256>>>(
        (uint32_t*)p_h2h, nullptr, (uint32_t*)p_wvh, nullptr,
        b_v, nullptr, nullptr, (uint32_t*)p_v16, nullptr, 512, 0, 128, 1.f);
    gemm16p<false, false, false, false, 1><<<dim3(4, 96), 256>>>(
        (uint32_t*)p_gsh, nullptr, (uint32_t*)p_wvgh, nullptr,
        nullptr, nullptr, nullptr, (uint32_t*)p_vg16, nullptr, 256, 0, 128, 1.f);

    // 3b) combined V transpose (fp16 copy)
    pack_v_kernel<<<HH*128*NN/256, 256>>>();

    // 4) register-resident fp16 flash attention
    cudaFuncSetAttribute(attn_reg_kernel, cudaFuncAttributeMaxDynamicSharedMemorySize,
                         AT2_SMEM_BYTES);
    attn_reg_kernel<<<dim3(NN/ATQ, HH), 128, AT2_SMEM_BYTES>>>();

    // 5) h path
    gemm16p<false, true, true, false, 1><<<dim3(4, 32), 256>>>(
        (uint32_t*)p_outv16, nullptr, (uint32_t*)p_wngh, nullptr,
        b_ng, (const float*)p_hsrc, nullptr, (uint32_t*)p_hnew16, nullptr, 256, 256, 128, 1.f);
    gemm16p<false, true, false, false, 0><<<dim3(4, 32), 256>>>(
        (uint32_t*)p_hnew16, nullptr, (uint32_t*)p_whdech, nullptr,
        b_hdec, nullptr, out + NR*MM, nullptr, nullptr, 256, 0, 256, 1.f);

    // 6) g path
    gemm16p<false, false, true, false, 0><<<dim3(4, 96), 256>>>(
        (uint32_t*)p_outg16, nullptr, (uint32_t*)p_wgouth, nullptr,
        nullptr, (const float*)p_gsrc, (float*)p_gnew, nullptr, nullptr, 256, 256, 256, 1.f);
    gdec_kernel<<<NR/16, 256>>>(W_gdec, out);
}

// round 13
// speedup vs baseline: 1.0861x; 1.0861x over previous
#include <cuda_runtime.h>
#include <cuda_fp16.h>
#include <math.h>
#include <stdint.h>

// Shapes (fixed for this problem)
#define NN   4096
#define NV   3
#define MM   16
#define EE   256
#define HH   8
#define DD   32
#define NR   (NN*NV)
#define SQRT_E 16.0f
#define SCALING 0.17677669529663687f   // 32^-0.5

// ---------------- scratch (device globals; no allocation allowed) -------------
__device__ float d_g_src[NR*EE];                       // fp32 (gram input, gout residual)
__device__ __align__(16) uint32_t d_gsh[NR*128];       // g_src fp16 [row][128 w]
__device__ float d_hsrc[NN*EE];                        // h_src fp32 (ng residual)
__device__ __align__(16) uint32_t d_h2h[NN*256];       // h2 hi [node][256 w]
__device__ __align__(16) uint32_t d_h2l[NN*256];
__device__ __align__(16) uint32_t d_gramh[NN*512];
__device__ __align__(16) uint32_t d_graml[NN*512];
__device__ __align__(16) uint32_t d_t1h[NN*256];
__device__ __align__(16) uint32_t d_t1l[NN*256];
__device__ __align__(16) uint32_t d_qh[NN*128];
__device__ __align__(16) uint32_t d_ql[NN*128];
__device__ __align__(16) uint32_t d_kh[NN*128];
__device__ __align__(16) uint32_t d_kl[NN*128];
__device__ __align__(16) uint32_t d_v16[NN*128];
__device__ __align__(16) uint32_t d_vg16[NR*128];
__device__ __align__(16) __half  d_vt[HH*128*NN];      // combined V transposed [h][c][node]
__device__ __align__(16) uint32_t d_outv16[NN*128];
__device__ __align__(16) uint32_t d_outg16[NR*128];
__device__ __align__(16) uint32_t d_hnew16[NN*128];
__device__ float d_gnew[NR*EE];
// packed weights (transposed [n][k/2 words])
__device__ __align__(16) uint32_t d_wg1h[512*512], d_wg1l[512*512];
__device__ __align__(16) uint32_t d_wg2h[256*256], d_wg2l[256*256];
__device__ __align__(16) uint32_t d_wqh[256*256],  d_wql[256*256];
__device__ __align__(16) uint32_t d_wkh[256*256],  d_wkl[256*256];
__device__ __align__(16) uint32_t d_wvh[256*256];
__device__ __align__(16) uint32_t d_wvgh[256*128];
__device__ __align__(16) uint32_t d_wngh[256*128];
__device__ __align__(16) uint32_t d_wgouth[256*128];
__device__ __align__(16) uint32_t d_whdech[256*128];

// ---------------- helpers ------------------------------------------------------
__device__ __forceinline__ uint32_t packh2(__half a, __half b) {
    __half2 t = __halves2half2(a, b);
    return *reinterpret_cast<uint32_t*>(&t);
}
__device__ __forceinline__ uint32_t cvth(float a, float b) {
    __half2 t = __floats2half2_rn(a, b);
    return *reinterpret_cast<uint32_t*>(&t);
}
__device__ __forceinline__ void cvthl(float a, float b, uint32_t& hi, uint32_t& lo) {
    __half ha = __float2half_rn(a), hb = __float2half_rn(b);
    __half la = __float2half_rn(a - __half2float(ha));
    __half lb = __float2half_rn(b - __half2float(hb));
    hi = packh2(ha, hb);
    lo = packh2(la, lb);
}

__device__ __forceinline__ void mma_f16(float c[4],
    uint32_t a0, uint32_t a1, uint32_t a2, uint32_t a3,
    uint32_t b0, uint32_t b1)
{
    asm volatile(
        "mma.sync.aligned.m16n8k16.row.col.f32.f16.f16.f32 "
        "{%0,%1,%2,%3}, {%4,%5,%6,%7}, {%8,%9}, {%0,%1,%2,%3};\n"
        : "+f"(c[0]), "+f"(c[1]), "+f"(c[2]), "+f"(c[3])
        : "r"(a0), "r"(a1), "r"(a2), "r"(a3), "r"(b0), "r"(b1));
}

__device__ __forceinline__ void ldsm4(uint32_t& r0, uint32_t& r1,
                                      uint32_t& r2, uint32_t& r3, const void* p)
{
    uint32_t addr = (uint32_t)__cvta_generic_to_shared(p);
    asm volatile("ldmatrix.sync.aligned.m8n8.x4.shared.b16 {%0,%1,%2,%3}, [%4];"
                 : "=r"(r0), "=r"(r1), "=r"(r2), "=r"(r3) : "r"(addr));
}

// ---------------- fused weight pre-pack (ONE launch, tiled transpose) ----------
struct WEnt { const float* W; uint32_t* Wh; uint32_t* Wl; int K; int Nn; int x2; int base; };
struct WArgs { WEnt e[9]; };

__global__ __launch_bounds__(256)
void packall_kernel(WArgs a)
{
    __shared__ float sw[64][33];
    int b = blockIdx.x;
    int ei = 0;
#pragma unroll
    for (int i = 1; i < 9; i++) if (b >= a.e[i].base) ei = i;
    WEnt we = a.e[ei];
    int t = b - we.base;
    int ktiles = we.K >> 6;
    int kt = t % ktiles, nt = t / ktiles;
    int tid = threadIdx.x;

    // coalesced read: 64 k-rows x 32 n
#pragma unroll
    for (int l = 0; l < 8; l++) {
        int idx = tid + l*256;
        int k = idx >> 5, n = idx & 31;
        sw[k][n] = we.W[(kt*64 + k)*we.Nn + nt*32 + n];
    }
    __syncthreads();

    int n = tid >> 3, g4 = tid & 7;
    int K2w = we.K >> 1;
    uint32_t hi[4], lo[4];
#pragma unroll
    for (int i = 0; i < 4; i++) {
        int kp = g4*4 + i;
        float x = sw[2*kp][n], y = sw[2*kp+1][n];
        if (we.x2) cvthl(x, y, hi[i], lo[i]);
        else       hi[i] = cvth(x, y);
    }
    int off = (nt*32 + n)*K2w + kt*32 + g4*4;
    *(uint4*)&we.Wh[off] = make_uint4(hi[0], hi[1], hi[2], hi[3]);
    if (we.x2) *(uint4*)&we.Wl[off] = make_uint4(lo[0], lo[1], lo[2], lo[3]);
}

// ---------------- g_src = (equ @ W_equ) * 16  (+ fp16 copy) --------------------
__global__ void gsrc_kernel(const float* __restrict__ equ,
                            const float* __restrict__ W_equ)
{
    __shared__ float es[MM];
    int r = blockIdx.x;
    int e = threadIdx.x;
    if (e < MM) es[e] = equ[r*MM + e];
    __syncthreads();
    float acc = 0.f;
#pragma unroll
    for (int m = 0; m < MM; m++) acc += es[m] * W_equ[m*EE + e];
    d_g_src[r*EE + e] = acc * SQRT_E;
    ((__half*)d_gsh)[r*EE + e] = __float2half_rn(acc * SQRT_E);
}

// ---------------- h_src = h*16  (fp32 + packed hi/lo into h2 right half) -------
__global__ void hsrc_kernel(const float* __restrict__ h)
{
    int i = blockIdx.x, e = threadIdx.x;
    float v = h[i*EE + e] * SQRT_E;
    d_hsrc[i*EE + e] = v;
    __half hi = __float2half_rn(v);
    __half lo = __float2half_rn(v - __half2float(hi));
    ((__half*)d_h2h)[i*512 + 256 + e] = hi;
    ((__half*)d_h2l)[i*512 + 256 + e] = lo;
}

// ---------------- g2p + Gram (emit packed hi/lo) -------------------------------
__global__ void gram_kernel(const float* __restrict__ W_gproj)
{
    __shared__ float gs[NV][EE];
    __shared__ float g2p[NV][32];
    int node = blockIdx.x;
    int t = threadIdx.x;
#pragma unroll
    for (int i = 0; i < NV; i++) gs[i][t] = d_g_src[(node*NV + i)*EE + t];
    __syncthreads();
    if (t < 96) {
        int i = t >> 5, a = t & 31;
        float acc = 0.f;
#pragma unroll 4
        for (int k2 = 0; k2 < EE; k2++) acc += gs[i][k2] * W_gproj[k2*32 + a];
        g2p[i][a] = acc;
    }
    __syncthreads();
#pragma unroll
    for (int o2 = t; o2 < 512; o2 += 256) {
        int e0 = 2*o2;
        int a = e0 >> 5, b = e0 & 31;
        float v0 = g2p[0][a]*g2p[0][b]   + g2p[1][a]*g2p[1][b]   + g2p[2][a]*g2p[2][b];
        float v1 = g2p[0][a]*g2p[0][b+1] + g2p[1][a]*g2p[1][b+1] + g2p[2][a]*g2p[2][b+1];
        cvthl(v0, v1, d_gramh[node*512 + o2], d_graml[node*512 + o2]);
    }
}

// ---------------- fully-packed fp16 tensor-core GEMM ---------------------------
// A: [M][K/2 words] hi(/lo).  B: [n][K/2 words] hi(/lo) (pre-transposed weights).
// EMIT 0: fp32 C (ldc floats).  EMIT 1: fp16 Ch (ldc words).  EMIT 2: hi/lo.
template<bool RELU, bool BIAS, bool RES, bool X2, int EMIT>
__global__ __launch_bounds__(256, 2)
void gemm16p(const uint32_t* __restrict__ Ah, const uint32_t* __restrict__ Al,
             const uint32_t* __restrict__ Bh, const uint32_t* __restrict__ Bl,
             const float* __restrict__ bias, const float* __restrict__ resid,
             float* __restrict__ C, uint32_t* __restrict__ Ch, uint32_t* __restrict__ Cl,
             int K, int ldr, int ldc, float alpha)
{
    __shared__ uint32_t Ahi[128][20];
    __shared__ uint32_t Alo[X2 ? 128 : 1][20];
    __shared__ uint32_t Bhi[64][20];
    __shared__ uint32_t Blo[X2 ? 64 : 1][20];

    int tid = threadIdx.x, lane = tid & 31, w = tid >> 5;
    int m0 = blockIdx.y * 128, n0 = blockIdx.x * 64;
    int rw = (w >> 1) * 32;
    int cw = (w & 1) * 32;
    int g  = lane >> 3;
    int K2w = K >> 1;

    int afr = tid >> 1;            // A fill: row 0..127
    int afw = (tid & 1) * 8;       // A fill: word base {0,8}
    int bfr = tid >> 2;            // B fill: row n 0..63
    int bfw = (tid & 3) * 4;       // B fill: word base

    float acc[2][4][4] = {};
    uint4 pah0, pah1, pal0, pal1, pbh, pbl;

    // prologue prefetch (k0w = 0)
    {
        const uint4* ap = (const uint4*)&Ah[(uint64_t)(m0 + afr)*K2w + afw];
        pah0 = ap[0]; pah1 = ap[1];
        pbh  = *(const uint4*)&Bh[(n0 + bfr)*K2w + bfw];
        if (X2) {
            const uint4* alp = (const uint4*)&Al[(uint64_t)(m0 + afr)*K2w + afw];
            pal0 = alp[0]; pal1 = alp[1];
            pbl  = *(const uint4*)&Bl[(n0 + bfr)*K2w + bfw];
        }
    }

    for (int k0w = 0; k0w < K2w; k0w += 16) {
        __syncthreads();
        *(uint4*)&Ahi[afr][afw]     = pah0;
        *(uint4*)&Ahi[afr][afw + 4] = pah1;
        *(uint4*)&Bhi[bfr][bfw]     = pbh;
        if (X2) {
            *(uint4*)&Alo[afr][afw]     = pal0;
            *(uint4*)&Alo[afr][afw + 4] = pal1;
            *(uint4*)&Blo[bfr][bfw]     = pbl;
        }
        __syncthreads();
        if (k0w + 16 < K2w) {
            const uint4* ap = (const uint4*)&Ah[(uint64_t)(m0 + afr)*K2w + k0w + 16 + afw];
            pah0 = ap[0]; pah1 = ap[1];
            pbh  = *(const uint4*)&Bh[(n0 + bfr)*K2w + k0w + 16 + bfw];
            if (X2) {
                const uint4* alp = (const uint4*)&Al[(uint64_t)(m0 + afr)*K2w + k0w + 16 + afw];
                pal0 = alp[0]; pal1 = alp[1];
                pbl  = *(const uint4*)&Bl[(n0 + bfr)*K2w + k0w + 16 + bfw];
            }
        }
#pragma unroll
        for (int kk = 0; kk < 2; kk++) {
            int arow = rw + (g&1)*8 + (lane&7);
            int acol = kk*8 + (g>>1)*4;
            uint32_t ah[2][4], al[2][4];
            ldsm4(ah[0][0],ah[0][1],ah[0][2],ah[0][3], &Ahi[arow][acol]);
            ldsm4(ah[1][0],ah[1][1],ah[1][2],ah[1][3], &Ahi[arow+16][acol]);
            if (X2) {
                ldsm4(al[0][0],al[0][1],al[0][2],al[0][3], &Alo[arow][acol]);
                ldsm4(al[1][0],al[1][1],al[1][2],al[1][3], &Alo[arow+16][acol]);
            }
            uint32_t bh[8], bl[8];
#pragma unroll
            for (int jj = 0; jj < 2; jj++) {
                int brow = cw + jj*16 + (g>>1)*8 + (lane&7);
                int bcol = kk*8 + (g&1)*4;
                ldsm4(bh[jj*4+0],bh[jj*4+1],bh[jj*4+2],bh[jj*4+3], &Bhi[brow][bcol]);
                if (X2)
                    ldsm4(bl[jj*4+0],bl[jj*4+1],bl[jj*4+2],bl[jj*4+3], &Blo[brow][bcol]);
            }
#pragma unroll
            for (int t = 0; t < 2; t++) {
#pragma unroll
                for (int j = 0; j < 4; j++) {
                    uint32_t b0 = bh[(j>>1)*4 + (j&1)*2], b1 = bh[(j>>1)*4 + (j&1)*2 + 1];
                    mma_f16(acc[t][j], ah[t][0],ah[t][1],ah[t][2],ah[t][3], b0, b1);
                    if (X2) {
                        uint32_t c0 = bl[(j>>1)*4 + (j&1)*2], c1 = bl[(j>>1)*4 + (j&1)*2 + 1];
                        mma_f16(acc[t][j], al[t][0],al[t][1],al[t][2],al[t][3], b0, b1);
                        mma_f16(acc[t][j], ah[t][0],ah[t][1],ah[t][2],ah[t][3], c0, c1);
                    }
                }
            }
        }
    }

    // epilogue
#pragma unroll
    for (int t = 0; t < 2; t++) {
        int r0 = m0 + rw + t*16 + (lane >> 2);
#pragma unroll
        for (int j = 0; j < 4; j++) {
            int col = n0 + cw + j*8 + 2*(lane & 3);
            float b0 = 0.f, b1 = 0.f;
            if (BIAS) { b0 = bias[col]; b1 = bias[col+1]; }
#pragma unroll
            for (int h2r = 0; h2r < 2; h2r++) {
                int row = r0 + h2r*8;
                float v0 = acc[t][j][2*h2r+0];
                float v1 = acc[t][j][2*h2r+1];
                if (BIAS) { v0 += b0; v1 += b1; }
                v0 *= alpha; v1 *= alpha;
                if (RES) {
                    v0 += resid[row*ldr + col];
                    v1 += resid[row*ldr + col + 1];
                }
                if (RELU) { v0 = fmaxf(v0, 0.f); v1 = fmaxf(v1, 0.f); }
                if (EMIT == 0) {
                    *(float2*)&C[row*ldc + col] = make_float2(v0, v1);
                } else if (EMIT == 1) {
                    Ch[row*ldc + (col >> 1)] = cvth(v0, v1);
                } else {
                    cvthl(v0, v1, Ch[row*ldc + (col >> 1)], Cl[row*ldc + (col >> 1)]);
                }
            }
        }
    }
}

// ---------------- combined-V transpose (smem tiles, coalesced both ways) -------
// dest d_vt[h][c][node]; source d_v16 [node][128w] / d_vg16 [node*NV+iv][128w]
__global__ __launch_bounds__(256)
void packv_kernel()
{
    __shared__ __half sv[32][72];
    int b = blockIdx.x;
    int h  = b >> 8;
    int t  = b & 255;
    int c0 = (t >> 6) * 32;
    int n0 = (t & 63) * 64;
    int tid = threadIdx.x;

    // read: 64 nodes x 16 words (64B per node, coalesced)
#pragma unroll
    for (int l = 0; l < 4; l++) {
        int idx = tid + l*256;
        int node = idx >> 4, cwi = idx & 15;
        uint32_t wv;
        if (c0 < 32) {
            wv = d_v16[(n0 + node)*128 + h*16 + cwi];
        } else {
            int iv = (c0 - 32) >> 5;
            wv = d_vg16[((n0 + node)*NV + iv)*128 + h*16 + cwi];
        }
        __half2 hv = *(__half2*)&wv;
        sv[2*cwi    ][node] = __low2half(hv);
        sv[2*cwi + 1][node] = __high2half(hv);
    }
    __syncthreads();

    // write: 32 c x 64 nodes, uint4 (8 nodes) per thread, coalesced
    int c = tid >> 3, ng = tid & 7;
    uint4 o;
    o.x = packh2(sv[c][ng*8+0], sv[c][ng*8+1]);
    o.y = packh2(sv[c][ng*8+2], sv[c][ng*8+3]);
    o.z = packh2(sv[c][ng*8+4], sv[c][ng*8+5]);
    o.w = packh2(sv[c][ng*8+6], sv[c][ng*8+7]);
    *(uint4*)&d_vt[(h*128 + c0 + c)*NN + n0 + ng*8] = o;
}

// ---------------- register-resident fp16 flash attention -----------------------
#define ATQ 64
#define ATK 64
#define AT2_SMEM_BYTES ((64*20*2 + 128*36)*4)

__global__ __launch_bounds__(128, 4)
void attn_reg_kernel()
{
    extern __shared__ char smc[];
    uint32_t* KH = (uint32_t*)smc;                // [64][20] half2
    uint32_t* KL = KH + 64*20;
    uint32_t* VT = KL + 64*20;                    // [128][36] half2 (n-major, k contig)

    int tid  = threadIdx.x;
    int lane = tid & 31;
    int w    = tid >> 5;
    int g    = lane >> 3;
    int hh   = blockIdx.y;
    int hoff = hh * DD;
    int hw   = hh * 16;          // head word offset
    int qbase = blockIdx.x * ATQ;
    int wbase = w * 16;

    // ---- preload Q fragments (already packed hi/lo) ----
    uint32_t qh[2][4], ql[2][4];
    {
        int gr0 = qbase + wbase + (lane >> 2);
#pragma unroll
        for (int kk = 0; kk < 2; kk++) {
            int w0 = hw + kk*8 + (lane & 3);
            qh[kk][0] = d_qh[gr0*128 + w0];
            qh[kk][1] = d_qh[(gr0+8)*128 + w0];
            qh[kk][2] = d_qh[gr0*128 + w0 + 4];
            qh[kk][3] = d_qh[(gr0+8)*128 + w0 + 4];
            ql[kk][0] = d_ql[gr0*128 + w0];
            ql[kk][1] = d_ql[(gr0+8)*128 + w0];
            ql[kk][2] = d_ql[gr0*128 + w0 + 4];
            ql[kk][3] = d_ql[(gr0+8)*128 + w0 + 4];
        }
    }

    float rmax0 = -1e30f, rmax1 = -1e30f;
    float rsum0 = 0.f, rsum1 = 0.f;
    float acc[16][4] = {};

    for (int kb = 0; kb < NN; kb += ATK) {
        __syncthreads();
#pragma unroll
        for (int l = 0; l < 4; l++) {
            int idx = tid + l*128;
            int row = idx >> 3, cp = (idx & 7) * 2;
            int gg = (kb + row)*128 + hw + cp;
            *(uint2*)&KH[row*20 + cp] = *(const uint2*)&d_kh[gg];
            *(uint2*)&KL[row*20 + cp] = *(const uint2*)&d_kl[gg];
        }
#pragma unroll
        for (int l = 0; l < 8; l++) {
            int idx = tid + l*128;
            int row = idx >> 3;
            int c16 = idx & 7;
            uint4 vv = *(const uint4*)&d_vt[(hh*128 + row)*NN + kb + c16*8];
            *(uint4*)&VT[row*36 + c16*4] = vv;
        }
        __syncthreads();

        // ---- S = Q K^T (fp16 hi/lo) ----
        float sc[8][4];
#pragma unroll
        for (int j = 0; j < 8; j++)
#pragma unroll
            for (int i = 0; i < 4; i++) sc[j][i] = 0.f;
#pragma unroll
        for (int kk = 0; kk < 2; kk++) {
#pragma unroll
            for (int jj = 0; jj < 4; jj++) {
                int nrow = jj*16 + (g>>1)*8 + (lane&7);
                int kc   = kk*8 + (g&1)*4;
                uint32_t bh[4], bl[4];
                ldsm4(bh[0],bh[1],bh[2],bh[3], &KH[nrow*20 + kc]);
                ldsm4(bl[0],bl[1],bl[2],bl[3], &KL[nrow*20 + kc]);
#pragma unroll
                for (int jw = 0; jw < 2; jw++) {
                    int j = 2*jj + jw;
                    uint32_t b0 = bh[jw*2], b1 = bh[jw*2+1];
                    uint32_t c0 = bl[jw*2], c1 = bl[jw*2+1];
                    mma_f16(sc[j], qh[kk][0], qh[kk][1], qh[kk][2], qh[kk][3], b0, b1);
                    mma_f16(sc[j], ql[kk][0], ql[kk][1], ql[kk][2], ql[kk][3], b0, b1);
                    mma_f16(sc[j], qh[kk][0], qh[kk][1], qh[kk][2], qh[kk][3], c0, c1);
                }
            }
        }

        // ---- online softmax in registers; skip rescale if no new max ----
        float m0 = rmax0, m1 = rmax1;
#pragma unroll
        for (int j = 0; j < 8; j++) {
            m0 = fmaxf(m0, fmaxf(sc[j][0], sc[j][1]));
            m1 = fmaxf(m1, fmaxf(sc[j][2], sc[j][3]));
        }
        m0 = fmaxf(m0, __shfl_xor_sync(0xffffffffu, m0, 1));
        m0 = fmaxf(m0, __shfl_xor_sync(0xffffffffu, m0, 2));
        m1 = fmaxf(m1, __shfl_xor_sync(0xffffffffu, m1, 1));
        m1 = fmaxf(m1, __shfl_xor_sync(0xffffffffu, m1, 2));

        bool nm = __any_sync(0xffffffffu, (m0 > rmax0) || (m1 > rmax1));
        if (nm) {
            float alf0 = __expf(rmax0 - m0);
            float alf1 = __expf(rmax1 - m1);
            rsum0 *= alf0; rsum1 *= alf1;
#pragma unroll
            for (int j = 0; j < 16; j++) {
                acc[j][0] *= alf0; acc[j][1] *= alf0;
                acc[j][2] *= alf1; acc[j][3] *= alf1;
            }
            rmax0 = m0; rmax1 = m1;
        }

        uint32_t pp0[8], pp1[8];
        float ps0 = 0.f, ps1 = 0.f;
#pragma unroll
        for (int j = 0; j < 8; j++) {
            float pa = __expf(sc[j][0] - rmax0);
            float pb = __expf(sc[j][1] - rmax0);
            float pc = __expf(sc[j][2] - rmax1);
            float pd = __expf(sc[j][3] - rmax1);
            pp0[j] = cvth(pa, pb);
            pp1[j] = cvth(pc, pd);
            ps0 += pa + pb;
            ps1 += pc + pd;
        }
        ps0 += __shfl_xor_sync(0xffffffffu, ps0, 1);
        ps0 += __shfl_xor_sync(0xffffffffu, ps0, 2);
        ps1 += __shfl_xor_sync(0xffffffffu, ps1, 1);
        ps1 += __shfl_xor_sync(0xffffffffu, ps1, 2);
        rsum0 += ps0;
        rsum1 += ps1;

        // ---- P@V (single fp16) ----
#pragma unroll
        for (int kk = 0; kk < 4; kk++) {
            uint32_t a0 = pp0[2*kk],   a1 = pp1[2*kk];
            uint32_t a2 = pp0[2*kk+1], a3 = pp1[2*kk+1];
#pragma unroll
            for (int jj = 0; jj < 8; jj++) {
                int nrow = jj*16 + (g>>1)*8 + (lane&7);
                int kc   = kk*8 + (g&1)*4;
                uint32_t b[4];
                ldsm4(b[0], b[1], b[2], b[3], &VT[nrow*36 + kc]);
                mma_f16(acc[2*jj],   a0, a1, a2, a3, b[0], b[1]);
                mma_f16(acc[2*jj+1], a0, a1, a2, a3, b[2], b[3]);
            }
        }
    }

    // ---- epilogue: normalize, emit fp16 packed ----
    {
        float inv0 = 1.0f / rsum0;
        float inv1 = 1.0f / rsum1;
        int gr0 = qbase + wbase + (lane >> 2);
        int gr1 = gr0 + 8;
#pragma unroll
        for (int j = 0; j < 16; j++) {
            int col = j*8 + 2*(lane & 3);
            uint32_t w0 = cvth(acc[j][0]*inv0, acc[j][1]*inv0);
            uint32_t w1 = cvth(acc[j][2]*inv1, acc[j][3]*inv1);
            if (col < 32) {
                d_outv16[gr0*128 + ((hoff + col) >> 1)] = w0;
                d_outv16[gr1*128 + ((hoff + col) >> 1)] = w1;
            } else {
                int iv = (col - 32) >> 5, dc = (col - 32) & 31;
                d_outg16[(gr0*NV + iv)*128 + ((hoff + dc) >> 1)] = w0;
                d_outg16[(gr1*NV + iv)*128 + ((hoff + dc) >> 1)] = w1;
            }
        }
    }
}

// ---------------- equ_out = gnew @ W_gdec  ([*,256]@[256,16]) ------------------
__global__ void gdec_kernel(const float* __restrict__ W_gdec, float* __restrict__ out)
{
    __shared__ float gs[16][EE];
    int rbase = blockIdx.x * 16;
    int t = threadIdx.x;
    for (int idx = t; idx < 16*EE; idx += 256)
        gs[idx >> 8][idx & 255] = d_gnew[(rbase + (idx >> 8))*EE + (idx & 255)];
    __syncthreads();
    int lr = t >> 4, c = t & 15;
    float acc = 0.f;
#pragma unroll 4
    for (int k2 = 0; k2 < EE; k2++) acc += gs[lr][k2] * W_gdec[k2*MM + c];
    out[(rbase + lr)*MM + c] = acc;
}

// ------------------------------------------------------------------------------
extern "C" void kernel_launch(void* const* d_in, const int* in_sizes, int n_in,
                              void* d_out, int out_size)
{
    const float* equ    = (const float*)d_in[0];
    const float* h      = (const float*)d_in[1];
    const float* W_equ  = (const float*)d_in[4];
    const float* W_gproj= (const float*)d_in[5];
    const float* W_vg   = (const float*)d_in[6];
    const float* W_g1   = (const float*)d_in[7];
    const float* b_g1   = (const float*)d_in[8];
    const float* W_g2   = (const float*)d_in[9];
    const float* b_g2   = (const float*)d_in[10];
    const float* W_q    = (const float*)d_in[11];
    const float* b_q    = (const float*)d_in[12];
    const float* W_k    = (const float*)d_in[13];
    const float* b_k    = (const float*)d_in[14];
    const float* W_v    = (const float*)d_in[15];
    const float* b_v    = (const float*)d_in[16];
    const float* W_ng   = (const float*)d_in[17];
    const float* b_ng   = (const float*)d_in[18];
    const float* W_gout = (const float*)d_in[19];
    const float* W_gdec = (const float*)d_in[20];
    const float* W_hdec = (const float*)d_in[21];
    const float* b_hdec = (const float*)d_in[22];
    float* out = (float*)d_out;

#define SYM(p, s) void* p; cudaGetSymbolAddress(&p, s)
    SYM(p_gsrc, d_g_src);  SYM(p_gsh, d_gsh);   SYM(p_hsrc, d_hsrc);
    SYM(p_h2h, d_h2h);     SYM(p_h2l, d_h2l);
    SYM(p_gramh, d_gramh); SYM(p_graml, d_graml);
    SYM(p_t1h, d_t1h);     SYM(p_t1l, d_t1l);
    SYM(p_qh, d_qh);       SYM(p_ql, d_ql);
    SYM(p_kh, d_kh);       SYM(p_kl, d_kl);
    SYM(p_v16, d_v16);     SYM(p_vg16, d_vg16);
    SYM(p_outv16, d_outv16); SYM(p_outg16, d_outg16);
    SYM(p_hnew16, d_hnew16); SYM(p_gnew, d_gnew);
    SYM(p_wg1h, d_wg1h); SYM(p_wg1l, d_wg1l);
    SYM(p_wg2h, d_wg2h); SYM(p_wg2l, d_wg2l);
    SYM(p_wqh, d_wqh);   SYM(p_wql, d_wql);
    SYM(p_wkh, d_wkh);   SYM(p_wkl, d_wkl);
    SYM(p_wvh, d_wvh);   SYM(p_wvgh, d_wvgh);
    SYM(p_wngh, d_wngh); SYM(p_wgouth, d_wgouth);
    SYM(p_whdech, d_whdech);
#undef SYM

    // 0) fused weight pre-pack (one launch)
    WArgs wa;
    // entry: W, Wh, Wl, K, Nn, x2, base.  tiles = (K/64)*(Nn/32)
    wa.e[0] = { W_g1,  (uint32_t*)p_wg1h,  (uint32_t*)p_wg1l,  1024, 512, 1, 0   };  // 256
    wa.e[1] = { W_g2,  (uint32_t*)p_wg2h,  (uint32_t*)p_wg2l,  512,  256, 1, 256 };  // 64
    wa.e[2] = { W_q,   (uint32_t*)p_wqh,   (uint32_t*)p_wql,   512,  256, 1, 320 };  // 64
    wa.e[3] = { W_k,   (uint32_t*)p_wkh,   (uint32_t*)p_wkl,   512,  256, 1, 384 };  // 64
    wa.e[4] = { W_v,   (uint32_t*)p_wvh,   nullptr,            512,  256, 0, 448 };  // 64
    wa.e[5] = { W_vg,  (uint32_t*)p_wvgh,  nullptr,            256,  256, 0, 512 };  // 32
    wa.e[6] = { W_ng,  (uint32_t*)p_wngh,  nullptr,            256,  256, 0, 544 };  // 32
    wa.e[7] = { W_gout,(uint32_t*)p_wgouth,nullptr,            256,  256, 0, 576 };  // 32
    wa.e[8] = { W_hdec,(uint32_t*)p_whdech,nullptr,            256,  256, 0, 608 };  // 32
    packall_kernel<<<640, 256>>>(wa);

    // 1) prep
    gsrc_kernel<<<NR, 256>>>(equ, W_equ);
    hsrc_kernel<<<NN, 256>>>(h);
    gram_kernel<<<NN, 256>>>(W_gproj);

    // 2) MLP on gram (X2, emit packed)
    gemm16p<true, true, false, true, 2><<<dim3(8, 32), 256>>>(
        (uint32_t*)p_gramh, (uint32_t*)p_graml, (uint32_t*)p_wg1h, (uint32_t*)p_wg1l,
        b_g1, nullptr, nullptr, (uint32_t*)p_t1h, (uint32_t*)p_t1l, 1024, 0, 256, 1.f);
    gemm16p<false, true, false, true, 2><<<dim3(4, 32), 256>>>(
        (uint32_t*)p_t1h, (uint32_t*)p_t1l, (uint32_t*)p_wg2h, (uint32_t*)p_wg2l,
        b_g2, nullptr, nullptr, (uint32_t*)p_h2h, (uint32_t*)p_h2l, 512, 0, 256, 1.f);

    // 3) q,k (X2 -> packed hi/lo), v,vg (single -> fp16)
    gemm16p<false, true, false, true, 2><<<dim3(4, 32), 256>>>(
        (uint32_t*)p_h2h, (uint32_t*)p_h2l, (uint32_t*)p_wqh, (uint32_t*)p_wql,
        b_q, nullptr, nullptr, (uint32_t*)p_qh, (uint32_t*)p_ql, 512, 0, 128, SCALING);
    gemm16p<false, true, false, true, 2><<<dim3(4, 32), 256>>>(
        (uint32_t*)p_h2h, (uint32_t*)p_h2l, (uint32_t*)p_wkh, (uint32_t*)p_wkl,
        b_k, nullptr, nullptr, (uint32_t*)p_kh, (uint32_t*)p_kl, 512, 0, 128, 1.f);
    gemm16p<false, true, false, false, 1><<<dim3(4, 32), 256>>>(
        (uint32_t*)p_h2h, nullptr, (uint32_t*)p_wvh, nullptr,
        b_v, nullptr, nullptr, (uint32_t*)p_v16, nullptr, 512, 0, 128, 1.f);
    gemm16p<false, false, false, false, 1><<<dim3(4, 96), 256>>>(
        (uint32_t*)p_gsh, nullptr, (uint32_t*)p_wvgh, nullptr,
        nullptr, nullptr, nullptr, (uint32_t*)p_vg16, nullptr, 256, 0, 128, 1.f);

    // 3b) combined V transpose (tiled, coalesced)
    packv_kernel<<<HH*256, 256>>>();

    // 4) register-resident fp16 flash attention (single wave: 4 CTAs/SM)
    cudaFuncSetAttribute(attn_reg_kernel, cudaFuncAttributeMaxDynamicSharedMemorySize,
                         AT2_SMEM_BYTES);
    attn_reg_kernel<<<dim3(NN/ATQ, HH), 128, AT2_SMEM_BYTES>>>();

    // 5) h path
    gemm16p<false, true, true, false, 1><<<dim3(4, 32), 256>>>(
        (uint32_t*)p_outv16, nullptr, (uint32_t*)p_wngh, nullptr,
        b_ng, (const float*)p_hsrc, nullptr, (uint32_t*)p_hnew16, nullptr, 256, 256, 128, 1.f);
    gemm16p<false, true, false, false, 0><<<dim3(4, 32), 256>>>(
        (uint32_t*)p_hnew16, nullptr, (uint32_t*)p_whdech, nullptr,
        b_hdec, nullptr, out + NR*MM, nullptr, nullptr, 256, 0, 256, 1.f);

    // 6) g path
    gemm16p<false, false, true, false, 0><<<dim3(4, 96), 256>>>(
        (uint32_t*)p_outg16, nullptr, (uint32_t*)p_wgouth, nullptr,
        nullptr, (const float*)p_gsrc, (float*)p_gnew, nullptr, nullptr, 256, 256, 256, 1.f);
    gdec_kernel<<<NR/16, 256>>>(W_gdec, out);
}

// round 14
// speedup vs baseline: 1.3022x; 1.1989x over previous
#include <cuda_runtime.h>
#include <cuda_fp16.h>
#include <math.h>
#include <stdint.h>

// Shapes (fixed for this problem)
#define NN   4096
#define NV   3
#define MM   16
#define EE   256
#define HH   8
#define DD   32
#define NR   (NN*NV)
#define SQRT_E 16.0f
#define SCALING 0.17677669529663687f   // 32^-0.5

// ---------------- scratch (device globals; no allocation allowed) -------------
__device__ float d_g_src[NR*EE];                       // fp32 (g2p input, gout residual)
__device__ __align__(16) uint32_t d_gsh[NR*128];       // g_src fp16 [row][128 w]
__device__ float d_hsrc[NN*EE];                        // h_src fp32 (ng residual)
__device__ float d_g2p[NR*32];                         // g_src @ W_gproj (fp32)
__device__ __align__(16) uint32_t d_h2h[NN*256];       // h2 hi [node][256 w]
__device__ __align__(16) uint32_t d_h2l[NN*256];
__device__ __align__(16) uint32_t d_gramh[NN*512];
__device__ __align__(16) uint32_t d_t1h[NN*256];
__device__ __align__(16) uint32_t d_qh[NN*128];
__device__ __align__(16) uint32_t d_ql[NN*128];
__device__ __align__(16) uint32_t d_kh[NN*128];
__device__ __align__(16) uint32_t d_kl[NN*128];
__device__ __align__(16) uint32_t d_v16[NN*128];
__device__ __align__(16) uint32_t d_vg16[NR*128];
__device__ __align__(16) __half  d_vt[HH*128*NN];      // combined V transposed [h][c][node]
__device__ __align__(16) uint32_t d_outv16[NN*128];
__device__ __align__(16) uint32_t d_outg16[NR*128];
__device__ __align__(16) uint32_t d_hnew16[NN*128];
__device__ float d_gnew[NR*EE];
// packed weights (transposed [n][k/2 words])
__device__ __align__(16) uint32_t d_wg1h[512*512];
__device__ __align__(16) uint32_t d_wg2h[256*256];
__device__ __align__(16) uint32_t d_wqh[256*256],  d_wql[256*256];
__device__ __align__(16) uint32_t d_wkh[256*256],  d_wkl[256*256];
__device__ __align__(16) uint32_t d_wvh[256*256];
__device__ __align__(16) uint32_t d_wvgh[256*128];
__device__ __align__(16) uint32_t d_wngh[256*128];
__device__ __align__(16) uint32_t d_wgouth[256*128];
__device__ __align__(16) uint32_t d_whdech[256*128];

// ---------------- helpers ------------------------------------------------------
__device__ __forceinline__ uint32_t packh2(__half a, __half b) {
    __half2 t = __halves2half2(a, b);
    return *reinterpret_cast<uint32_t*>(&t);
}
__device__ __forceinline__ uint32_t cvth(float a, float b) {
    __half2 t = __floats2half2_rn(a, b);
    return *reinterpret_cast<uint32_t*>(&t);
}
__device__ __forceinline__ void cvthl(float a, float b, uint32_t& hi, uint32_t& lo) {
    __half ha = __float2half_rn(a), hb = __float2half_rn(b);
    __half la = __float2half_rn(a - __half2float(ha));
    __half lb = __float2half_rn(b - __half2float(hb));
    hi = packh2(ha, hb);
    lo = packh2(la, lb);
}

__device__ __forceinline__ void mma_f16(float c[4],
    uint32_t a0, uint32_t a1, uint32_t a2, uint32_t a3,
    uint32_t b0, uint32_t b1)
{
    asm volatile(
        "mma.sync.aligned.m16n8k16.row.col.f32.f16.f16.f32 "
        "{%0,%1,%2,%3}, {%4,%5,%6,%7}, {%8,%9}, {%0,%1,%2,%3};\n"
        : "+f"(c[0]), "+f"(c[1]), "+f"(c[2]), "+f"(c[3])
        : "r"(a0), "r"(a1), "r"(a2), "r"(a3), "r"(b0), "r"(b1));
}

__device__ __forceinline__ void ldsm4(uint32_t& r0, uint32_t& r1,
                                      uint32_t& r2, uint32_t& r3, const void* p)
{
    uint32_t addr = (uint32_t)__cvta_generic_to_shared(p);
    asm volatile("ldmatrix.sync.aligned.m8n8.x4.shared.b16 {%0,%1,%2,%3}, [%4];"
                 : "=r"(r0), "=r"(r1), "=r"(r2), "=r"(r3) : "r"(addr));
}

// ---------------- fused weight pre-pack (ONE launch, tiled transpose) ----------
struct WEnt { const float* W; uint32_t* Wh; uint32_t* Wl; int K; int Nn; int x2; int base; };
struct WArgs { WEnt e[9]; };

__global__ __launch_bounds__(256)
void packall_kernel(WArgs a)
{
    __shared__ float sw[64][33];
    int b = blockIdx.x;
    int ei = 0;
#pragma unroll
    for (int i = 1; i < 9; i++) if (b >= a.e[i].base) ei = i;
    WEnt we = a.e[ei];
    int t = b - we.base;
    int ktiles = we.K >> 6;
    int kt = t % ktiles, nt = t / ktiles;
    int tid = threadIdx.x;

#pragma unroll
    for (int l = 0; l < 8; l++) {
        int idx = tid + l*256;
        int k = idx >> 5, n = idx & 31;
        sw[k][n] = we.W[(kt*64 + k)*we.Nn + nt*32 + n];
    }
    __syncthreads();

    int n = tid >> 3, g4 = tid & 7;
    int K2w = we.K >> 1;
    uint32_t hi[4], lo[4];
#pragma unroll
    for (int i = 0; i < 4; i++) {
        int kp = g4*4 + i;
        float x = sw[2*kp][n], y = sw[2*kp+1][n];
        if (we.x2) cvthl(x, y, hi[i], lo[i]);
        else       hi[i] = cvth(x, y);
    }
    int off = (nt*32 + n)*K2w + kt*32 + g4*4;
    *(uint4*)&we.Wh[off] = make_uint4(hi[0], hi[1], hi[2], hi[3]);
    if (we.x2) *(uint4*)&we.Wl[off] = make_uint4(lo[0], lo[1], lo[2], lo[3]);
}

// ---------------- g_src = (equ @ W_equ) * 16  (+ fp16 copy) --------------------
__global__ void gsrc_kernel(const float* __restrict__ equ,
                            const float* __restrict__ W_equ)
{
    __shared__ float es[MM];
    int r = blockIdx.x;
    int e = threadIdx.x;
    if (e < MM) es[e] = equ[r*MM + e];
    __syncthreads();
    float acc = 0.f;
#pragma unroll
    for (int m = 0; m < MM; m++) acc += es[m] * W_equ[m*EE + e];
    d_g_src[r*EE + e] = acc * SQRT_E;
    ((__half*)d_gsh)[r*EE + e] = __float2half_rn(acc * SQRT_E);
}

// ---------------- h_src = h*16  (fp32 + packed hi/lo into h2 right half) -------
__global__ void hsrc_kernel(const float* __restrict__ h)
{
    int i = blockIdx.x, e = threadIdx.x;
    float v = h[i*EE + e] * SQRT_E;
    d_hsrc[i*EE + e] = v;
    __half hi = __float2half_rn(v);
    __half lo = __float2half_rn(v - __half2float(hi));
    ((__half*)d_h2h)[i*512 + 256 + e] = hi;
    ((__half*)d_h2l)[i*512 + 256 + e] = lo;
}

// ---------------- g2p = g_src @ W_gproj (warp = 8 rows, ILP-8) -----------------
__global__ __launch_bounds__(256)
void g2p_kernel(const float* __restrict__ Wg)
{
    __shared__ float sW[256][32];
    int tid = threadIdx.x;
#pragma unroll
    for (int l = 0; l < 8; l++) {
        int idx = tid + l*256;
        int k = idx >> 3, c4 = (idx & 7) * 4;
        *(float4*)&sW[k][c4] = *(const float4*)&Wg[k*32 + c4];
    }
    __syncthreads();
    int wid = tid >> 5, lane = tid & 31;
    int rbase = blockIdx.x*64 + wid*8;
    float acc[8] = {};
    for (int k0 = 0; k0 < 256; k0 += 32) {
        float wreg[32];
#pragma unroll
        for (int i = 0; i < 32; i++) wreg[i] = sW[k0 + i][lane];
#pragma unroll
        for (int rr = 0; rr < 8; rr++) {
            const float4* ap = (const float4*)&d_g_src[(rbase + rr)*256 + k0];
#pragma unroll
            for (int k4 = 0; k4 < 8; k4++) {
                float4 a = ap[k4];
                acc[rr] += a.x*wreg[k4*4] + a.y*wreg[k4*4+1]
                         + a.z*wreg[k4*4+2] + a.w*wreg[k4*4+3];
            }
        }
    }
#pragma unroll
    for (int rr = 0; rr < 8; rr++) d_g2p[(rbase + rr)*32 + lane] = acc[rr];
}

// ---------------- Gram outer products (8 nodes/block, emit fp16 hi) ------------
__global__ __launch_bounds__(256)
void gram2_kernel()
{
    __shared__ float sg[8][96];
    int node0 = blockIdx.x * 8;
    int tid = threadIdx.x;
#pragma unroll
    for (int l = 0; l < 3; l++) {
        int idx = tid + l*256;
        sg[idx/96][idx%96] = d_g2p[node0*96 + idx];
    }
    __syncthreads();
#pragma unroll
    for (int l = 0; l < 16; l++) {
        int idx = tid + l*256;               // over 8*512 words
        int nd = idx >> 9, o2 = idx & 511;
        int e0 = o2*2;
        int a = e0 >> 5, b = e0 & 31;
        const float* g = sg[nd];
        float v0 = g[a]*g[b]   + g[32+a]*g[32+b]   + g[64+a]*g[64+b];
        float v1 = g[a]*g[b+1] + g[32+a]*g[32+b+1] + g[64+a]*g[64+b+1];
        d_gramh[(node0 + nd)*512 + o2] = cvth(v0, v1);
    }
}

// ---------------- fully-packed fp16 tensor-core GEMM ---------------------------
// A: [M][K/2 words] hi(/lo).  B: [n][K/2 words] hi(/lo) (pre-transposed weights).
// EMIT 0: fp32 C (ldc floats).  EMIT 1: fp16 Ch (ldc words).  EMIT 2: hi/lo.
template<bool RELU, bool BIAS, bool RES, bool X2, int EMIT>
__global__ __launch_bounds__(256, 2)
void gemm16p(const uint32_t* __restrict__ Ah, const uint32_t* __restrict__ Al,
             const uint32_t* __restrict__ Bh, const uint32_t* __restrict__ Bl,
             const float* __restrict__ bias, const float* __restrict__ resid,
             float* __restrict__ C, uint32_t* __restrict__ Ch, uint32_t* __restrict__ Cl,
             int K, int ldr, int ldc, float alpha)
{
    __shared__ uint32_t Ahi[128][20];
    __shared__ uint32_t Alo[X2 ? 128 : 1][20];
    __shared__ uint32_t Bhi[64][20];
    __shared__ uint32_t Blo[X2 ? 64 : 1][20];

    int tid = threadIdx.x, lane = tid & 31, w = tid >> 5;
    int m0 = blockIdx.y * 128, n0 = blockIdx.x * 64;
    int rw = (w >> 1) * 32;
    int cw = (w & 1) * 32;
    int g  = lane >> 3;
    int K2w = K >> 1;

    int afr = tid >> 1;
    int afw = (tid & 1) * 8;
    int bfr = tid >> 2;
    int bfw = (tid & 3) * 4;

    float acc[2][4][4] = {};
    uint4 pah0, pah1, pal0, pal1, pbh, pbl;

    {
        const uint4* ap = (const uint4*)&Ah[(uint64_t)(m0 + afr)*K2w + afw];
        pah0 = ap[0]; pah1 = ap[1];
        pbh  = *(const uint4*)&Bh[(n0 + bfr)*K2w + bfw];
        if (X2) {
            const uint4* alp = (const uint4*)&Al[(uint64_t)(m0 + afr)*K2w + afw];
            pal0 = alp[0]; pal1 = alp[1];
            pbl  = *(const uint4*)&Bl[(n0 + bfr)*K2w + bfw];
        }
    }

    for (int k0w = 0; k0w < K2w; k0w += 16) {
        __syncthreads();
        *(uint4*)&Ahi[afr][afw]     = pah0;
        *(uint4*)&Ahi[afr][afw + 4] = pah1;
        *(uint4*)&Bhi[bfr][bfw]     = pbh;
        if (X2) {
            *(uint4*)&Alo[afr][afw]     = pal0;
            *(uint4*)&Alo[afr][afw + 4] = pal1;
            *(uint4*)&Blo[bfr][bfw]     = pbl;
        }
        __syncthreads();
        if (k0w + 16 < K2w) {
            const uint4* ap = (const uint4*)&Ah[(uint64_t)(m0 + afr)*K2w + k0w + 16 + afw];
            pah0 = ap[0]; pah1 = ap[1];
            pbh  = *(const uint4*)&Bh[(n0 + bfr)*K2w + k0w + 16 + bfw];
            if (X2) {
                const uint4* alp = (const uint4*)&Al[(uint64_t)(m0 + afr)*K2w + k0w + 16 + afw];
                pal0 = alp[0]; pal1 = alp[1];
                pbl  = *(const uint4*)&Bl[(n0 + bfr)*K2w + k0w + 16 + bfw];
            }
        }
#pragma unroll
        for (int kk = 0; kk < 2; kk++) {
            int arow = rw + (g&1)*8 + (lane&7);
            int acol = kk*8 + (g>>1)*4;
            uint32_t ah[2][4], al[2][4];
            ldsm4(ah[0][0],ah[0][1],ah[0][2],ah[0][3], &Ahi[arow][acol]);
            ldsm4(ah[1][0],ah[1][1],ah[1][2],ah[1][3], &Ahi[arow+16][acol]);
            if (X2) {
                ldsm4(al[0][0],al[0][1],al[0][2],al[0][3], &Alo[arow][acol]);
                ldsm4(al[1][0],al[1][1],al[1][2],al[1][3], &Alo[arow+16][acol]);
            }
            uint32_t bh[8], bl[8];
#pragma unroll
            for (int jj = 0; jj < 2; jj++) {
                int brow = cw + jj*16 + (g>>1)*8 + (lane&7);
                int bcol = kk*8 + (g&1)*4;
                ldsm4(bh[jj*4+0],bh[jj*4+1],bh[jj*4+2],bh[jj*4+3], &Bhi[brow][bcol]);
                if (X2)
                    ldsm4(bl[jj*4+0],bl[jj*4+1],bl[jj*4+2],bl[jj*4+3], &Blo[brow][bcol]);
            }
#pragma unroll
            for (int t = 0; t < 2; t++) {
#pragma unroll
                for (int j = 0; j < 4; j++) {
                    uint32_t b0 = bh[(j>>1)*4 + (j&1)*2], b1 = bh[(j>>1)*4 + (j&1)*2 + 1];
                    mma_f16(acc[t][j], ah[t][0],ah[t][1],ah[t][2],ah[t][3], b0, b1);
                    if (X2) {
                        uint32_t c0 = bl[(j>>1)*4 + (j&1)*2], c1 = bl[(j>>1)*4 + (j&1)*2 + 1];
                        mma_f16(acc[t][j], al[t][0],al[t][1],al[t][2],al[t][3], b0, b1);
                        mma_f16(acc[t][j], ah[t][0],ah[t][1],ah[t][2],ah[t][3], c0, c1);
                    }
                }
            }
        }
    }

#pragma unroll
    for (int t = 0; t < 2; t++) {
        int r0 = m0 + rw + t*16 + (lane >> 2);
#pragma unroll
        for (int j = 0; j < 4; j++) {
            int col = n0 + cw + j*8 + 2*(lane & 3);
            float b0 = 0.f, b1 = 0.f;
            if (BIAS) { b0 = bias[col]; b1 = bias[col+1]; }
#pragma unroll
            for (int h2r = 0; h2r < 2; h2r++) {
                int row = r0 + h2r*8;
                float v0 = acc[t][j][2*h2r+0];
                float v1 = acc[t][j][2*h2r+1];
                if (BIAS) { v0 += b0; v1 += b1; }
                v0 *= alpha; v1 *= alpha;
                if (RES) {
                    v0 += resid[row*ldr + col];
                    v1 += resid[row*ldr + col + 1];
                }
                if (RELU) { v0 = fmaxf(v0, 0.f); v1 = fmaxf(v1, 0.f); }
                if (EMIT == 0) {
                    *(float2*)&C[row*ldc + col] = make_float2(v0, v1);
                } else if (EMIT == 1) {
                    Ch[row*ldc + (col >> 1)] = cvth(v0, v1);
                } else {
                    cvthl(v0, v1, Ch[row*ldc + (col >> 1)], Cl[row*ldc + (col >> 1)]);
                }
            }
        }
    }
}

// ---------------- combined-V transpose (smem tiles, coalesced both ways) -------
__global__ __launch_bounds__(256)
void packv_kernel()
{
    __shared__ __half sv[32][72];
    int b = blockIdx.x;
    int h  = b >> 8;
    int t  = b & 255;
    int c0 = (t >> 6) * 32;
    int n0 = (t & 63) * 64;
    int tid = threadIdx.x;

#pragma unroll
    for (int l = 0; l < 4; l++) {
        int idx = tid + l*256;
        int node = idx >> 4, cwi = idx & 15;
        uint32_t wv;
        if (c0 < 32) {
            wv = d_v16[(n0 + node)*128 + h*16 + cwi];
        } else {
            int iv = (c0 - 32) >> 5;
            wv = d_vg16[((n0 + node)*NV + iv)*128 + h*16 + cwi];
        }
        __half2 hv = *(__half2*)&wv;
        sv[2*cwi    ][node] = __low2half(hv);
        sv[2*cwi + 1][node] = __high2half(hv);
    }
    __syncthreads();

    int c = tid >> 3, ng = tid & 7;
    uint4 o;
    o.x = packh2(sv[c][ng*8+0], sv[c][ng*8+1]);
    o.y = packh2(sv[c][ng*8+2], sv[c][ng*8+3]);
    o.z = packh2(sv[c][ng*8+4], sv[c][ng*8+5]);
    o.w = packh2(sv[c][ng*8+6], sv[c][ng*8+7]);
    *(uint4*)&d_vt[(h*128 + c0 + c)*NN + n0 + ng*8] = o;
}

// ---------------- register-resident fp16 flash attention (cp.async 2-stage) ----
#define ATQ 64
#define ATK 64
// per stage (words): KH 1280 | KL 1280 | VT 4608.  2 stages.
#define AT_ST_KH 0
#define AT_ST_KL 2560
#define AT_ST_VT 5120
#define AT2_SMEM_BYTES (2*(1280 + 1280 + 4608)*4)   // 57344

__global__ __launch_bounds__(128, 4)
void attn_reg_kernel()
{
    extern __shared__ char smc[];
    uint32_t* SB = (uint32_t*)smc;
    uint32_t smem_u32 = (uint32_t)__cvta_generic_to_shared(smc);

    int tid  = threadIdx.x;
    int lane = tid & 31;
    int w    = tid >> 5;
    int g    = lane >> 3;
    int hh   = blockIdx.y;
    int hoff = hh * DD;
    int hw   = hh * 16;
    int qbase = blockIdx.x * ATQ;
    int wbase = w * 16;

    // ---- preload Q fragments (already packed hi/lo) ----
    uint32_t qh[2][4], ql[2][4];
    {
        int gr0 = qbase + wbase + (lane >> 2);
#pragma unroll
        for (int kk = 0; kk < 2; kk++) {
            int w0 = hw + kk*8 + (lane & 3);
            qh[kk][0] = d_qh[gr0*128 + w0];
            qh[kk][1] = d_qh[(gr0+8)*128 + w0];
            qh[kk][2] = d_qh[gr0*128 + w0 + 4];
            qh[kk][3] = d_qh[(gr0+8)*128 + w0 + 4];
            ql[kk][0] = d_ql[gr0*128 + w0];
            ql[kk][1] = d_ql[(gr0+8)*128 + w0];
            ql[kk][2] = d_ql[gr0*128 + w0 + 4];
            ql[kk][3] = d_ql[(gr0+8)*128 + w0 + 4];
        }
    }

    // async fill of one stage
    auto fill = [&](int stage, int kb) {
        uint32_t khb = smem_u32 + (AT_ST_KH + stage*1280)*4;
        uint32_t klb = smem_u32 + (AT_ST_KL + stage*1280)*4;
        uint32_t vtb = smem_u32 + (AT_ST_VT + stage*4608)*4;
#pragma unroll
        for (int l = 0; l < 4; l++) {
            int idx = tid + l*128;
            int row = idx >> 3, cp = (idx & 7) * 2;
            int gg = (kb + row)*128 + hw + cp;
            asm volatile("cp.async.ca.shared.global [%0], [%1], 8;"
                         :: "r"(khb + (row*20 + cp)*4), "l"(&d_kh[gg]));
            asm volatile("cp.async.ca.shared.global [%0], [%1], 8;"
                         :: "r"(klb + (row*20 + cp)*4), "l"(&d_kl[gg]));
        }
#pragma unroll
        for (int l = 0; l < 8; l++) {
            int idx = tid + l*128;
            int row = idx >> 3, c16 = idx & 7;
            asm volatile("cp.async.cg.shared.global [%0], [%1], 16;"
                         :: "r"(vtb + (row*36 + c16*4)*4),
                            "l"(&d_vt[(hh*128 + row)*NN + kb + c16*8]));
        }
        asm volatile("cp.async.commit_group;");
    };

    float rmax0 = -1e30f, rmax1 = -1e30f;
    float rsum0 = 0.f, rsum1 = 0.f;
    float acc[16][4] = {};

    fill(0, 0);

    for (int it = 0; it < NN/ATK; it++) {
        int cur = it & 1;
        if (it + 1 < NN/ATK) {
            fill(cur ^ 1, (it + 1)*ATK);
            asm volatile("cp.async.wait_group 1;");
        } else {
            asm volatile("cp.async.wait_group 0;");
        }
        __syncthreads();
        uint32_t* KH = SB + AT_ST_KH + cur*1280;
        uint32_t* KL = SB + AT_ST_KL + cur*1280;
        uint32_t* VT = SB + AT_ST_VT + cur*4608;

        // ---- S = Q K^T (fp16 hi/lo) ----
        float sc[8][4];
#pragma unroll
        for (int j = 0; j < 8; j++)
#pragma unroll
            for (int i = 0; i < 4; i++) sc[j][i] = 0.f;
#pragma unroll
        for (int kk = 0; kk < 2; kk++) {
#pragma unroll
            for (int jj = 0; jj < 4; jj++) {
                int nrow = jj*16 + (g>>1)*8 + (lane&7);
                int kc   = kk*8 + (g&1)*4;
                uint32_t bh[4], bl[4];
                ldsm4(bh[0],bh[1],bh[2],bh[3], &KH[nrow*20 + kc]);
                ldsm4(bl[0],bl[1],bl[2],bl[3], &KL[nrow*20 + kc]);
#pragma unroll
                for (int jw = 0; jw < 2; jw++) {
                    int j = 2*jj + jw;
                    uint32_t b0 = bh[jw*2], b1 = bh[jw*2+1];
                    uint32_t c0 = bl[jw*2], c1 = bl[jw*2+1];
                    mma_f16(sc[j], qh[kk][0], qh[kk][1], qh[kk][2], qh[kk][3], b0, b1);
                    mma_f16(sc[j], ql[kk][0], ql[kk][1], ql[kk][2], ql[kk][3], b0, b1);
                    mma_f16(sc[j], qh[kk][0], qh[kk][1], qh[kk][2], qh[kk][3], c0, c1);
                }
            }
        }

        // ---- online softmax in registers; skip rescale if no new max ----
        float m0 = rmax0, m1 = rmax1;
#pragma unroll
        for (int j = 0; j < 8; j++) {
            m0 = fmaxf(m0, fmaxf(sc[j][0], sc[j][1]));
            m1 = fmaxf(m1, fmaxf(sc[j][2], sc[j][3]));
        }
        m0 = fmaxf(m0, __shfl_xor_sync(0xffffffffu, m0, 1));
        m0 = fmaxf(m0, __shfl_xor_sync(0xffffffffu, m0, 2));
        m1 = fmaxf(m1, __shfl_xor_sync(0xffffffffu, m1, 1));
        m1 = fmaxf(m1, __shfl_xor_sync(0xffffffffu, m1, 2));

        bool nm = __any_sync(0xffffffffu, (m0 > rmax0) || (m1 > rmax1));
        if (nm) {
            float alf0 = __expf(rmax0 - m0);
            float alf1 = __expf(rmax1 - m1);
            rsum0 *= alf0; rsum1 *= alf1;
#pragma unroll
            for (int j = 0; j < 16; j++) {
                acc[j][0] *= alf0; acc[j][1] *= alf0;
                acc[j][2] *= alf1; acc[j][3] *= alf1;
            }
            rmax0 = m0; rmax1 = m1;
        }

        uint32_t pp0[8], pp1[8];
        float ps0 = 0.f, ps1 = 0.f;
#pragma unroll
        for (int j = 0; j < 8; j++) {
            float pa = __expf(sc[j][0] - rmax0);
            float pb = __expf(sc[j][1] - rmax0);
            float pc = __expf(sc[j][2] - rmax1);
            float pd = __expf(sc[j][3] - rmax1);
            pp0[j] = cvth(pa, pb);
            pp1[j] = cvth(pc, pd);
            ps0 += pa + pb;
            ps1 += pc + pd;
        }
        ps0 += __shfl_xor_sync(0xffffffffu, ps0, 1);
        ps0 += __shfl_xor_sync(0xffffffffu, ps0, 2);
        ps1 += __shfl_xor_sync(0xffffffffu, ps1, 1);
        ps1 += __shfl_xor_sync(0xffffffffu, ps1, 2);
        rsum0 += ps0;
        rsum1 += ps1;

        // ---- P@V (single fp16) ----
#pragma unroll
        for (int kk = 0; kk < 4; kk++) {
            uint32_t a0 = pp0[2*kk],   a1 = pp1[2*kk];
            uint32_t a2 = pp0[2*kk+1], a3 = pp1[2*kk+1];
#pragma unroll
            for (int jj = 0; jj < 8; jj++) {
                int nrow = jj*16 + (g>>1)*8 + (lane&7);
                int kc   = kk*8 + (g&1)*4;
                uint32_t b[4];
                ldsm4(b[0], b[1], b[2], b[3], &VT[nrow*36 + kc]);
                mma_f16(acc[2*jj],   a0, a1, a2, a3, b[0], b[1]);
                mma_f16(acc[2*jj+1], a0, a1, a2, a3, b[2], b[3]);
            }
        }
        __syncthreads();
    }

    // ---- epilogue: normalize, emit fp16 packed ----
    {
        float inv0 = 1.0f / rsum0;
        float inv1 = 1.0f / rsum1;
        int gr0 = qbase + wbase + (lane >> 2);
        int gr1 = gr0 + 8;
#pragma unroll
        for (int j = 0; j < 16; j++) {
            int col = j*8 + 2*(lane & 3);
            uint32_t w0 = cvth(acc[j][0]*inv0, acc[j][1]*inv0);
            uint32_t w1 = cvth(acc[j][2]*inv1, acc[j][3]*inv1);
            if (col < 32) {
                d_outv16[gr0*128 + ((hoff + col) >> 1)] = w0;
                d_outv16[gr1*128 + ((hoff + col) >> 1)] = w1;
            } else {
                int iv = (col - 32) >> 5, dc = (col - 32) & 31;
                d_outg16[(gr0*NV + iv)*128 + ((hoff + dc) >> 1)] = w0;
                d_outg16[(gr1*NV + iv)*128 + ((hoff + dc) >> 1)] = w1;
            }
        }
    }
}

// ---------------- equ_out = gnew @ W_gdec  ([*,256]@[256,16], ILP-4) -----------
__global__ void gdec_kernel(const float* __restrict__ W_gdec, float* __restrict__ out)
{
    __shared__ float gs[16][EE];
    int rbase = blockIdx.x * 16;
    int t = threadIdx.x;
    for (int idx = t; idx < 16*EE; idx += 256)
        gs[idx >> 8][idx & 255] = d_gnew[(rbase + (idx >> 8))*EE + (idx & 255)];
    __syncthreads();
    int lr = t >> 4, c = t & 15;
    float a0 = 0.f, a1 = 0.f, a2 = 0.f, a3 = 0.f;
#pragma unroll 8
    for (int k2 = 0; k2 < EE; k2 += 4) {
        a0 += gs[lr][k2+0] * W_gdec[(k2+0)*MM + c];
        a1 += gs[lr][k2+1] * W_gdec[(k2+1)*MM + c];
        a2 += gs[lr][k2+2] * W_gdec[(k2+2)*MM + c];
        a3 += gs[lr][k2+3] * W_gdec[(k2+3)*MM + c];
    }
    out[(rbase + lr)*MM + c] = (a0 + a1) + (a2 + a3);
}

// ------------------------------------------------------------------------------
extern "C" void kernel_launch(void* const* d_in, const int* in_sizes, int n_in,
                              void* d_out, int out_size)
{
    const float* equ    = (const float*)d_in[0];
    const float* h      = (const float*)d_in[1];
    const float* W_equ  = (const float*)d_in[4];
    const float* W_gproj= (const float*)d_in[5];
    const float* W_vg   = (const float*)d_in[6];
    const float* W_g1   = (const float*)d_in[7];
    const float* b_g1   = (const float*)d_in[8];
    const float* W_g2   = (const float*)d_in[9];
    const float* b_g2   = (const float*)d_in[10];
    const float* W_q    = (const float*)d_in[11];
    const float* b_q    = (const float*)d_in[12];
    const float* W_k    = (const float*)d_in[13];
    const float* b_k    = (const float*)d_in[14];
    const float* W_v    = (const float*)d_in[15];
    const float* b_v    = (const float*)d_in[16];
    const float* W_ng   = (const float*)d_in[17];
    const float* b_ng   = (const float*)d_in[18];
    const float* W_gout = (const float*)d_in[19];
    const float* W_gdec = (const float*)d_in[20];
    const float* W_hdec = (const float*)d_in[21];
    const float* b_hdec = (const float*)d_in[22];
    float* out = (float*)d_out;

#define SYM(p, s) void* p; cudaGetSymbolAddress(&p, s)
    SYM(p_gsrc, d_g_src);  SYM(p_gsh, d_gsh);   SYM(p_hsrc, d_hsrc);
    SYM(p_h2h, d_h2h);     SYM(p_h2l, d_h2l);
    SYM(p_gramh, d_gramh);
    SYM(p_t1h, d_t1h);
    SYM(p_qh, d_qh);       SYM(p_ql, d_ql);
    SYM(p_kh, d_kh);       SYM(p_kl, d_kl);
    SYM(p_v16, d_v16);     SYM(p_vg16, d_vg16);
    SYM(p_outv16, d_outv16); SYM(p_outg16, d_outg16);
    SYM(p_hnew16, d_hnew16); SYM(p_gnew, d_gnew);
    SYM(p_wg1h, d_wg1h);
    SYM(p_wg2h, d_wg2h);
    SYM(p_wqh, d_wqh);   SYM(p_wql, d_wql);
    SYM(p_wkh, d_wkh);   SYM(p_wkl, d_wkl);
    SYM(p_wvh, d_wvh);   SYM(p_wvgh, d_wvgh);
    SYM(p_wngh, d_wngh); SYM(p_wgouth, d_wgouth);
    SYM(p_whdech, d_whdech);
#undef SYM

    // 0) fused weight pre-pack (one launch)
    WArgs wa;
    wa.e[0] = { W_g1,  (uint32_t*)p_wg1h,  nullptr,            1024, 512, 0, 0   };  // 256
    wa.e[1] = { W_g2,  (uint32_t*)p_wg2h,  nullptr,            512,  256, 0, 256 };  // 64
    wa.e[2] = { W_q,   (uint32_t*)p_wqh,   (uint32_t*)p_wql,   512,  256, 1, 320 };  // 64
    wa.e[3] = { W_k,   (uint32_t*)p_wkh,   (uint32_t*)p_wkl,   512,  256, 1, 384 };  // 64
    wa.e[4] = { W_v,   (uint32_t*)p_wvh,   nullptr,            512,  256, 0, 448 };  // 64
    wa.e[5] = { W_vg,  (uint32_t*)p_wvgh,  nullptr,            256,  256, 0, 512 };  // 32
    wa.e[6] = { W_ng,  (uint32_t*)p_wngh,  nullptr,            256,  256, 0, 544 };  // 32
    wa.e[7] = { W_gout,(uint32_t*)p_wgouth,nullptr,            256,  256, 0, 576 };  // 32
    wa.e[8] = { W_hdec,(uint32_t*)p_whdech,nullptr,            256,  256, 0, 608 };  // 32
    packall_kernel<<<640, 256>>>(wa);

    // 1) prep
    gsrc_kernel<<<NR, 256>>>(equ, W_equ);
    hsrc_kernel<<<NN, 256>>>(h);
    g2p_kernel<<<NR/64, 256>>>(W_gproj);
    gram2_kernel<<<NN/8, 256>>>();

    // 2) MLP on gram (single fp16; g2 emits hi/lo for q/k)
    gemm16p<true, true, false, false, 1><<<dim3(8, 32), 256>>>(
        (uint32_t*)p_gramh, nullptr, (uint32_t*)p_wg1h, nullptr,
        b_g1, nullptr, nullptr, (uint32_t*)p_t1h, nullptr, 1024, 0, 256, 1.f);
    gemm16p<false, true, false, false, 2><<<dim3(4, 32), 256>>>(
        (uint32_t*)p_t1h, nullptr, (uint32_t*)p_wg2h, nullptr,
        b_g2, nullptr, nullptr, (uint32_t*)p_h2h, (uint32_t*)p_h2l, 512, 0, 256, 1.f);

    // 3) q,k (X2 -> packed hi/lo), v,vg (single -> fp16)
    gemm16p<false, true, false, true, 2><<<dim3(4, 32), 256>>>(
        (uint32_t*)p_h2h, (uint32_t*)p_h2l, (uint32_t*)p_wqh, (uint32_t*)p_wql,
        b_q, nullptr, nullptr, (uint32_t*)p_qh, (uint32_t*)p_ql, 512, 0, 128, SCALING);
    gemm16p<false, true, false, true, 2><<<dim3(4, 32), 256>>>(
        (uint32_t*)p_h2h, (uint32_t*)p_h2l, (uint32_t*)p_wkh, (uint32_t*)p_wkl,
        b_k, nullptr, nullptr, (uint32_t*)p_kh, (uint32_t*)p_kl, 512, 0, 128, 1.f);
    gemm16p<false, true, false, false, 1><<<dim3(4, 32), 256>>>(
        (uint32_t*)p_h2h, nullptr, (uint32_t*)p_wvh, nullptr,
        b_v, nullptr, nullptr, (uint32_t*)p_v16, nullptr, 512, 0, 128, 1.f);
    gemm16p<false, false, false, false, 1><<<dim3(4, 96), 256>>>(
        (uint32_t*)p_gsh, nullptr, (uint32_t*)p_wvgh, nullptr,
        nullptr, nullptr, nullptr, (uint32_t*)p_vg16, nullptr, 256, 0, 128, 1.f);

    // 3b) combined V transpose (tiled, coalesced)
    packv_kernel<<<HH*256, 256>>>();

    // 4) register-resident fp16 flash attention (cp.async 2-stage, single wave)
    cudaFuncSetAttribute(attn_reg_kernel, cudaFuncAttributeMaxDynamicSharedMemorySize,
                         AT2_SMEM_BYTES);
    attn_reg_kernel<<<dim3(NN/ATQ, HH), 128, AT2_SMEM_BYTES>>>();

    // 5) h path
    gemm16p<false, true, true, false, 1><<<dim3(4, 32), 256>>>(
        (uint32_t*)p_outv16, nullptr, (uint32_t*)p_wngh, nullptr,
        b_ng, (const float*)p_hsrc, nullptr, (uint32_t*)p_hnew16, nullptr, 256, 256, 128, 1.f);
    gemm16p<false, true, false, false, 0><<<dim3(4, 32), 256>>>(
        (uint32_t*)p_hnew16, nullptr, (uint32_t*)p_whdech, nullptr,
        b_hdec, nullptr, out + NR*MM, nullptr, nullptr, 256, 0, 256, 1.f);

    // 6) g path
    gemm16p<false, false, true, false, 0><<<dim3(4, 96), 256>>>(
        (uint32_t*)p_outg16, nullptr, (uint32_t*)p_wgouth, nullptr,
        nullptr, (const float*)p_gsrc, (float*)p_gnew, nullptr, nullptr, 256, 256, 256, 1.f);
    gdec_kernel<<<NR/16, 256>>>(W_gdec, out);
}

// round 16
// speedup vs baseline: 1.3752x; 1.0561x over previous
#include <cuda_runtime.h>
#include <cuda_fp16.h>
#include <math.h>
#include <stdint.h>

// Shapes (fixed for this problem)
#define NN   4096
#define NV   3
#define MM   16
#define EE   256
#define HH   8
#define DD   32
#define NR   (NN*NV)
#define SQRT_E 16.0f
#define SCALING 0.17677669529663687f   // 32^-0.5

// ---------------- scratch (device globals; no allocation allowed) -------------
__device__ __align__(16) uint32_t d_gsh[NR*128];       // g_src fp16 [row][128 w]
__device__ float d_hsrc[NN*EE];                        // h_src fp32 (ng residual)
__device__ __align__(16) uint32_t d_h2h[NN*256];       // h2 hi [node][256 w]
__device__ __align__(16) uint32_t d_h2l[NN*256];
__device__ __align__(16) uint32_t d_gramh[NN*512];
__device__ __align__(16) uint32_t d_t1h[NN*256];
__device__ __align__(16) uint32_t d_qh[NN*128];
__device__ __align__(16) uint32_t d_ql[NN*128];
__device__ __align__(16) uint32_t d_kh[NN*128];
__device__ __align__(16) uint32_t d_kl[NN*128];
__device__ __align__(16) uint32_t d_v16[NN*128];
__device__ __align__(16) uint32_t d_vg16[NR*128];
__device__ __align__(16) __half  d_vt[HH*128*NN];      // combined V transposed [h][c][node]
__device__ __align__(16) uint32_t d_outv16[NN*128];
__device__ __align__(16) uint32_t d_outg16[NR*128];
__device__ __align__(16) uint32_t d_hnew16[NN*128];
// combined small weights (fp32)
__device__ float d_wc_gp[16*32];    // 16 * W_equ @ W_gproj
__device__ float d_wc_gd[16*16];    // 16 * W_equ @ W_gdec
__device__ float d_wc_og[256*16];   // W_gout @ W_gdec
// packed weights (transposed [n][k/2 words])
__device__ __align__(16) uint32_t d_wg1h[512*512];
__device__ __align__(16) uint32_t d_wg2h[256*256];
__device__ __align__(16) uint32_t d_wqh[256*256],  d_wql[256*256];
__device__ __align__(16) uint32_t d_wkh[256*256],  d_wkl[256*256];
__device__ __align__(16) uint32_t d_wvh[256*256];
__device__ __align__(16) uint32_t d_wvgh[256*128];
__device__ __align__(16) uint32_t d_wngh[256*128];
__device__ __align__(16) uint32_t d_whdech[256*128];

// ---------------- helpers ------------------------------------------------------
__device__ __forceinline__ uint32_t packh2(__half a, __half b) {
    __half2 t = __halves2half2(a, b);
    return *reinterpret_cast<uint32_t*>(&t);
}
__device__ __forceinline__ uint32_t cvth(float a, float b) {
    __half2 t = __floats2half2_rn(a, b);
    return *reinterpret_cast<uint32_t*>(&t);
}
__device__ __forceinline__ void cvthl(float a, float b, uint32_t& hi, uint32_t& lo) {
    __half ha = __float2half_rn(a), hb = __float2half_rn(b);
    __half la = __float2half_rn(a - __half2float(ha));
    __half lb = __float2half_rn(b - __half2float(hb));
    hi = packh2(ha, hb);
    lo = packh2(la, lb);
}

__device__ __forceinline__ void mma_f16(float c[4],
    uint32_t a0, uint32_t a1, uint32_t a2, uint32_t a3,
    uint32_t b0, uint32_t b1)
{
    asm volatile(
        "mma.sync.aligned.m16n8k16.row.col.f32.f16.f16.f32 "
        "{%0,%1,%2,%3}, {%4,%5,%6,%7}, {%8,%9}, {%0,%1,%2,%3};\n"
        : "+f"(c[0]), "+f"(c[1]), "+f"(c[2]), "+f"(c[3])
        : "r"(a0), "r"(a1), "r"(a2), "r"(a3), "r"(b0), "r"(b1));
}

__device__ __forceinline__ void ldsm4(uint32_t& r0, uint32_t& r1,
                                      uint32_t& r2, uint32_t& r3, const void* p)
{
    uint32_t addr = (uint32_t)__cvta_generic_to_shared(p);
    asm volatile("ldmatrix.sync.aligned.m8n8.x4.shared.b16 {%0,%1,%2,%3}, [%4];"
                 : "=r"(r0), "=r"(r1), "=r"(r2), "=r"(r3) : "r"(addr));
}

// ---------------- fused weight pre-pack (ONE launch, tiled transpose) ----------
struct WEnt { const float* W; uint32_t* Wh; uint32_t* Wl; int K; int Nn; int x2; int base; };
struct WArgs { WEnt e[8]; };

__global__ __launch_bounds__(256)
void packall_kernel(WArgs a)
{
    __shared__ float sw[64][33];
    int b = blockIdx.x;
    int ei = 0;
#pragma unroll
    for (int i = 1; i < 8; i++) if (b >= a.e[i].base) ei = i;
    WEnt we = a.e[ei];
    int t = b - we.base;
    int ktiles = we.K >> 6;
    int kt = t % ktiles, nt = t / ktiles;
    int tid = threadIdx.x;

#pragma unroll
    for (int l = 0; l < 8; l++) {
        int idx = tid + l*256;
        int k = idx >> 5, n = idx & 31;
        sw[k][n] = we.W[(kt*64 + k)*we.Nn + nt*32 + n];
    }
    __syncthreads();

    int n = tid >> 3, g4 = tid & 7;
    int K2w = we.K >> 1;
    uint32_t hi[4], lo[4];
#pragma unroll
    for (int i = 0; i < 4; i++) {
        int kp = g4*4 + i;
        float x = sw[2*kp][n], y = sw[2*kp+1][n];
        if (we.x2) cvthl(x, y, hi[i], lo[i]);
        else       hi[i] = cvth(x, y);
    }
    int off = (nt*32 + n)*K2w + kt*32 + g4*4;
    *(uint4*)&we.Wh[off] = make_uint4(hi[0], hi[1], hi[2], hi[3]);
    if (we.x2) *(uint4*)&we.Wl[off] = make_uint4(lo[0], lo[1], lo[2], lo[3]);
}

// ---------------- combined small weights (one launch, 18 blocks) ---------------
__global__ __launch_bounds__(256)
void combw_kernel(const float* __restrict__ W_equ, const float* __restrict__ W_gproj,
                  const float* __restrict__ W_gdec, const float* __restrict__ W_gout)
{
    int b = blockIdx.x, t = threadIdx.x;
    if (b < 16) {
        // Wc_og[e][c] = sum_j W_gout[e][j] * W_gdec[j][c]
        int e = b*16 + (t >> 4), c = t & 15;
        float a0 = 0.f, a1 = 0.f, a2 = 0.f, a3 = 0.f;
#pragma unroll 8
        for (int j = 0; j < 256; j += 4) {
            a0 += W_gout[e*256 + j+0] * W_gdec[(j+0)*16 + c];
            a1 += W_gout[e*256 + j+1] * W_gdec[(j+1)*16 + c];
            a2 += W_gout[e*256 + j+2] * W_gdec[(j+2)*16 + c];
            a3 += W_gout[e*256 + j+3] * W_gdec[(j+3)*16 + c];
        }
        d_wc_og[e*16 + c] = (a0 + a1) + (a2 + a3);
    } else if (b == 16) {
        // Wc_gp[m][a] = 16 * sum_e W_equ[m][e] * W_gproj[e][a]
#pragma unroll
        for (int l = 0; l < 2; l++) {
            int idx = t + l*256;
            int m = idx >> 5, a = idx & 31;
            float a0 = 0.f, a1 = 0.f, a2 = 0.f, a3 = 0.f;
#pragma unroll 8
            for (int e = 0; e < 256; e += 4) {
                a0 += W_equ[m*256 + e+0] * W_gproj[(e+0)*32 + a];
                a1 += W_equ[m*256 + e+1] * W_gproj[(e+1)*32 + a];
                a2 += W_equ[m*256 + e+2] * W_gproj[(e+2)*32 + a];
                a3 += W_equ[m*256 + e+3] * W_gproj[(e+3)*32 + a];
            }
            d_wc_gp[idx] = ((a0 + a1) + (a2 + a3)) * SQRT_E;
        }
    } else {
        // Wc_gd[m][c] = 16 * sum_e W_equ[m][e] * W_gdec[e][c]
        int m = t >> 4, c = t & 15;
        float a0 = 0.f, a1 = 0.f, a2 = 0.f, a3 = 0.f;
#pragma unroll 8
        for (int e = 0; e < 256; e += 4) {
            a0 += W_equ[m*256 + e+0] * W_gdec[(e+0)*16 + c];
            a1 += W_equ[m*256 + e+1] * W_gdec[(e+1)*16 + c];
            a2 += W_equ[m*256 + e+2] * W_gdec[(e+2)*16 + c];
            a3 += W_equ[m*256 + e+3] * W_gdec[(e+3)*16 + c];
        }
        d_wc_gd[t] = ((a0 + a1) + (a2 + a3)) * SQRT_E;
    }
}

// ---------------- g_src fp16 = (equ @ W_equ) * 16 ------------------------------
__global__ void gsrc_kernel(const float* __restrict__ equ,
                            const float* __restrict__ W_equ)
{
    __shared__ float es[MM];
    int r = blockIdx.x;
    int e = threadIdx.x;
    if (e < MM) es[e] = equ[r*MM + e];
    __syncthreads();
    float acc = 0.f;
#pragma unroll
    for (int m = 0; m < MM; m++) acc += es[m] * W_equ[m*EE + e];
    ((__half*)d_gsh)[r*EE + e] = __float2half_rn(acc * SQRT_E);
}

// ---------------- h_src = h*16  (fp32 + packed hi/lo into h2 right half) -------
__global__ void hsrc_kernel(const float* __restrict__ h)
{
    int i = blockIdx.x, e = threadIdx.x;
    float v = h[i*EE + e] * SQRT_E;
    d_hsrc[i*EE + e] = v;
    __half hi = __float2half_rn(v);
    __half lo = __float2half_rn(v - __half2float(hi));
    ((__half*)d_h2h)[i*512 + 256 + e] = hi;
    ((__half*)d_h2l)[i*512 + 256 + e] = lo;
}

// ---------------- fused g2p + Gram (8 nodes/block, emit fp16 hi) ---------------
// g2p[r][a] = equ[r] . Wc_gp[.][a]  (K=16, Wc includes the *16 scale)
__global__ __launch_bounds__(256)
void gram_fused_kernel(const float* __restrict__ equ)
{
    __shared__ float swc[512];      // Wc_gp [16][32]
    __shared__ float se[8][48];
    __shared__ float sg[8][96];
    int node0 = blockIdx.x * 8;
    int tid = threadIdx.x;
    swc[tid] = d_wc_gp[tid];
    swc[tid + 256] = d_wc_gp[tid + 256];
    // FIX (R15 bug): cover all 384 equ elements with 256 threads
    for (int idx = tid; idx < 384; idx += 256)
        se[idx/48][idx%48] = equ[node0*48 + idx];
    __syncthreads();
#pragma unroll
    for (int l = 0; l < 3; l++) {
        int idx = tid + l*256;
        int nd = idx / 96, rest = idx % 96;
        int iv = rest >> 5, a = rest & 31;
        float acc = 0.f;
#pragma unroll
        for (int m = 0; m < 16; m++) acc += se[nd][iv*16 + m] * swc[m*32 + a];
        sg[nd][rest] = acc;
    }
    __syncthreads();
#pragma unroll
    for (int l = 0; l < 16; l++) {
        int idx = tid + l*256;               // over 8*512 words
        int nd = idx >> 9, o2 = idx & 511;
        int e0 = o2*2;
        int a = e0 >> 5, b = e0 & 31;
        const float* g = sg[nd];
        float v0 = g[a]*g[b]   + g[32+a]*g[32+b]   + g[64+a]*g[64+b];
        float v1 = g[a]*g[b+1] + g[32+a]*g[32+b+1] + g[64+a]*g[64+b+1];
        d_gramh[(node0 + nd)*512 + o2] = cvth(v0, v1);
    }
}

// ---------------- fully-packed fp16 tensor-core GEMM ---------------------------
template<bool RELU, bool BIAS, bool RES, bool X2, int EMIT>
__global__ __launch_bounds__(256, 2)
void gemm16p(const uint32_t* __restrict__ Ah, const uint32_t* __restrict__ Al,
             const uint32_t* __restrict__ Bh, const uint32_t* __restrict__ Bl,
             const float* __restrict__ bias, const float* __restrict__ resid,
             float* __restrict__ C, uint32_t* __restrict__ Ch, uint32_t* __restrict__ Cl,
             int K, int ldr, int ldc, float alpha)
{
    __shared__ uint32_t Ahi[128][20];
    __shared__ uint32_t Alo[X2 ? 128 : 1][20];
    __shared__ uint32_t Bhi[64][20];
    __shared__ uint32_t Blo[X2 ? 64 : 1][20];

    int tid = threadIdx.x, lane = tid & 31, w = tid >> 5;
    int m0 = blockIdx.y * 128, n0 = blockIdx.x * 64;
    int rw = (w >> 1) * 32;
    int cw = (w & 1) * 32;
    int g  = lane >> 3;
    int K2w = K >> 1;

    int afr = tid >> 1;
    int afw = (tid & 1) * 8;
    int bfr = tid >> 2;
    int bfw = (tid & 3) * 4;

    float acc[2][4][4] = {};
    uint4 pah0, pah1, pal0, pal1, pbh, pbl;

    {
        const uint4* ap = (const uint4*)&Ah[(uint64_t)(m0 + afr)*K2w + afw];
        pah0 = ap[0]; pah1 = ap[1];
        pbh  = *(const uint4*)&Bh[(n0 + bfr)*K2w + bfw];
        if (X2) {
            const uint4* alp = (const uint4*)&Al[(uint64_t)(m0 + afr)*K2w + afw];
            pal0 = alp[0]; pal1 = alp[1];
            pbl  = *(const uint4*)&Bl[(n0 + bfr)*K2w + bfw];
        }
    }

    for (int k0w = 0; k0w < K2w; k0w += 16) {
        __syncthreads();
        *(uint4*)&Ahi[afr][afw]     = pah0;
        *(uint4*)&Ahi[afr][afw + 4] = pah1;
        *(uint4*)&Bhi[bfr][bfw]     = pbh;
        if (X2) {
            *(uint4*)&Alo[afr][afw]     = pal0;
            *(uint4*)&Alo[afr][afw + 4] = pal1;
            *(uint4*)&Blo[bfr][bfw]     = pbl;
        }
        __syncthreads();
        if (k0w + 16 < K2w) {
            const uint4* ap = (const uint4*)&Ah[(uint64_t)(m0 + afr)*K2w + k0w + 16 + afw];
            pah0 = ap[0]; pah1 = ap[1];
            pbh  = *(const uint4*)&Bh[(n0 + bfr)*K2w + k0w + 16 + bfw];
            if (X2) {
                const uint4* alp = (const uint4*)&Al[(uint64_t)(m0 + afr)*K2w + k0w + 16 + afw];
                pal0 = alp[0]; pal1 = alp[1];
                pbl  = *(const uint4*)&Bl[(n0 + bfr)*K2w + k0w + 16 + bfw];
            }
        }
#pragma unroll
        for (int kk = 0; kk < 2; kk++) {
            int arow = rw + (g&1)*8 + (lane&7);
            int acol = kk*8 + (g>>1)*4;
            uint32_t ah[2][4], al[2][4];
            ldsm4(ah[0][0],ah[0][1],ah[0][2],ah[0][3], &Ahi[arow][acol]);
            ldsm4(ah[1][0],ah[1][1],ah[1][2],ah[1][3], &Ahi[arow+16][acol]);
            if (X2) {
                ldsm4(al[0][0],al[0][1],al[0][2],al[0][3], &Alo[arow][acol]);
                ldsm4(al[1][0],al[1][1],al[1][2],al[1][3], &Alo[arow+16][acol]);
            }
            uint32_t bh[8], bl[8];
#pragma unroll
            for (int jj = 0; jj < 2; jj++) {
                int brow = cw + jj*16 + (g>>1)*8 + (lane&7);
                int bcol = kk*8 + (g&1)*4;
                ldsm4(bh[jj*4+0],bh[jj*4+1],bh[jj*4+2],bh[jj*4+3], &Bhi[brow][bcol]);
                if (X2)
                    ldsm4(bl[jj*4+0],bl[jj*4+1],bl[jj*4+2],bl[jj*4+3], &Blo[brow][bcol]);
            }
#pragma unroll
            for (int t = 0; t < 2; t++) {
#pragma unroll
                for (int j = 0; j < 4; j++) {
                    uint32_t b0 = bh[(j>>1)*4 + (j&1)*2], b1 = bh[(j>>1)*4 + (j&1)*2 + 1];
                    mma_f16(acc[t][j], ah[t][0],ah[t][1],ah[t][2],ah[t][3], b0, b1);
                    if (X2) {
                        uint32_t c0 = bl[(j>>1)*4 + (j&1)*2], c1 = bl[(j>>1)*4 + (j&1)*2 + 1];
                        mma_f16(acc[t][j], al[t][0],al[t][1],al[t][2],al[t][3], b0, b1);
                        mma_f16(acc[t][j], ah[t][0],ah[t][1],ah[t][2],ah[t][3], c0, c1);
                    }
                }
            }
        }
    }

#pragma unroll
    for (int t = 0; t < 2; t++) {
        int r0 = m0 + rw + t*16 + (lane >> 2);
#pragma unroll
        for (int j = 0; j < 4; j++) {
            int col = n0 + cw + j*8 + 2*(lane & 3);
            float b0 = 0.f, b1 = 0.f;
            if (BIAS) { b0 = bias[col]; b1 = bias[col+1]; }
#pragma unroll
            for (int h2r = 0; h2r < 2; h2r++) {
                int row = r0 + h2r*8;
                float v0 = acc[t][j][2*h2r+0];
                float v1 = acc[t][j][2*h2r+1];
                if (BIAS) { v0 += b0; v1 += b1; }
                v0 *= alpha; v1 *= alpha;
                if (RES) {
                    v0 += resid[row*ldr + col];
                    v1 += resid[row*ldr + col + 1];
                }
                if (RELU) { v0 = fmaxf(v0, 0.f); v1 = fmaxf(v1, 0.f); }
                if (EMIT == 0) {
                    *(float2*)&C[row*ldc + col] = make_float2(v0, v1);
                } else if (EMIT == 1) {
                    Ch[row*ldc + (col >> 1)] = cvth(v0, v1);
                } else {
                    cvthl(v0, v1, Ch[row*ldc + (col >> 1)], Cl[row*ldc + (col >> 1)]);
                }
            }
        }
    }
}

// ---------------- combined-V transpose (smem tiles, coalesced both ways) -------
__global__ __launch_bounds__(256)
void packv_kernel()
{
    __shared__ __half sv[32][72];
    int b = blockIdx.x;
    int h  = b >> 8;
    int t  = b & 255;
    int c0 = (t >> 6) * 32;
    int n0 = (t & 63) * 64;
    int tid = threadIdx.x;

#pragma unroll
    for (int l = 0; l < 4; l++) {
        int idx = tid + l*256;
        int node = idx >> 4, cwi = idx & 15;
        uint32_t wv;
        if (c0 < 32) {
            wv = d_v16[(n0 + node)*128 + h*16 + cwi];
        } else {
            int iv = (c0 - 32) >> 5;
            wv = d_vg16[((n0 + node)*NV + iv)*128 + h*16 + cwi];
        }
        __half2 hv = *(__half2*)&wv;
        sv[2*cwi    ][node] = __low2half(hv);
        sv[2*cwi + 1][node] = __high2half(hv);
    }
    __syncthreads();

    int c = tid >> 3, ng = tid & 7;
    uint4 o;
    o.x = packh2(sv[c][ng*8+0], sv[c][ng*8+1]);
    o.y = packh2(sv[c][ng*8+2], sv[c][ng*8+3]);
    o.z = packh2(sv[c][ng*8+4], sv[c][ng*8+5]);
    o.w = packh2(sv[c][ng*8+6], sv[c][ng*8+7]);
    *(uint4*)&d_vt[(h*128 + c0 + c)*NN + n0 + ng*8] = o;
}

// ---------------- register-resident fp16 flash attention (cp.async 2-stage) ----
#define ATQ 64
#define ATK 64
#define AT_ST_KH 0
#define AT_ST_KL 2560
#define AT_ST_VT 5120
#define AT2_SMEM_BYTES (2*(1280 + 1280 + 4608)*4)   // 57344

__global__ __launch_bounds__(128, 4)
void attn_reg_kernel()
{
    extern __shared__ char smc[];
    uint32_t* SB = (uint32_t*)smc;
    uint32_t smem_u32 = (uint32_t)__cvta_generic_to_shared(smc);

    int tid  = threadIdx.x;
    int lane = tid & 31;
    int w    = tid >> 5;
    int g    = lane >> 3;
    int hh   = blockIdx.y;
    int hoff = hh * DD;
    int hw   = hh * 16;
    int qbase = blockIdx.x * ATQ;
    int wbase = w * 16;

    uint32_t qh[2][4], ql[2][4];
    {
        int gr0 = qbase + wbase + (lane >> 2);
#pragma unroll
        for (int kk = 0; kk < 2; kk++) {
            int w0 = hw + kk*8 + (lane & 3);
            qh[kk][0] = d_qh[gr0*128 + w0];
            qh[kk][1] = d_qh[(gr0+8)*128 + w0];
            qh[kk][2] = d_qh[gr0*128 + w0 + 4];
            qh[kk][3] = d_qh[(gr0+8)*128 + w0 + 4];
            ql[kk][0] = d_ql[gr0*128 + w0];
            ql[kk][1] = d_ql[(gr0+8)*128 + w0];
            ql[kk][2] = d_ql[gr0*128 + w0 + 4];
            ql[kk][3] = d_ql[(gr0+8)*128 + w0 + 4];
        }
    }

    auto fill = [&](int stage, int kb) {
        uint32_t khb = smem_u32 + (AT_ST_KH + stage*1280)*4;
        uint32_t klb = smem_u32 + (AT_ST_KL + stage*1280)*4;
        uint32_t vtb = smem_u32 + (AT_ST_VT + stage*4608)*4;
#pragma unroll
        for (int l = 0; l < 4; l++) {
            int idx = tid + l*128;
            int row = idx >> 3, cp = (idx & 7) * 2;
            int gg = (kb + row)*128 + hw + cp;
            asm volatile("cp.async.ca.shared.global [%0], [%1], 8;"
                         :: "r"(khb + (row*20 + cp)*4), "l"(&d_kh[gg]));
            asm volatile("cp.async.ca.shared.global [%0], [%1], 8;"
                         :: "r"(klb + (row*20 + cp)*4), "l"(&d_kl[gg]));
        }
#pragma unroll
        for (int l = 0; l < 8; l++) {
            int idx = tid + l*128;
            int row = idx >> 3, c16 = idx & 7;
            asm volatile("cp.async.cg.shared.global [%0], [%1], 16;"
                         :: "r"(vtb + (row*36 + c16*4)*4),
                            "l"(&d_vt[(hh*128 + row)*NN + kb + c16*8]));
        }
        asm volatile("cp.async.commit_group;");
    };

    float rmax0 = -1e30f, rmax1 = -1e30f;
    float rsum0 = 0.f, rsum1 = 0.f;
    float acc[16][4] = {};

    fill(0, 0);

    for (int it = 0; it < NN/ATK; it++) {
        int cur = it & 1;
        if (it + 1 < NN/ATK) {
            fill(cur ^ 1, (it + 1)*ATK);
            asm volatile("cp.async.wait_group 1;");
        } else {
            asm volatile("cp.async.wait_group 0;");
        }
        __syncthreads();
        uint32_t* KH = SB + AT_ST_KH + cur*1280;
        uint32_t* KL = SB + AT_ST_KL + cur*1280;
        uint32_t* VT = SB + AT_ST_VT + cur*4608;

        float sc[8][4];
#pragma unroll
        for (int j = 0; j < 8; j++)
#pragma unroll
            for (int i = 0; i < 4; i++) sc[j][i] = 0.f;
#pragma unroll
        for (int kk = 0; kk < 2; kk++) {
#pragma unroll
            for (int jj = 0; jj < 4; jj++) {
                int nrow = jj*16 + (g>>1)*8 + (lane&7);
                int kc   = kk*8 + (g&1)*4;
                uint32_t bh[4], bl[4];
                ldsm4(bh[0],bh[1],bh[2],bh[3], &KH[nrow*20 + kc]);
                ldsm4(bl[0],bl[1],bl[2],bl[3], &KL[nrow*20 + kc]);
#pragma unroll
                for (int jw = 0; jw < 2; jw++) {
                    int j = 2*jj + jw;
                    uint32_t b0 = bh[jw*2], b1 = bh[jw*2+1];
                    uint32_t c0 = bl[jw*2], c1 = bl[jw*2+1];
                    mma_f16(sc[j], qh[kk][0], qh[kk][1], qh[kk][2], qh[kk][3], b0, b1);
                    mma_f16(sc[j], ql[kk][0], ql[kk][1], ql[kk][2], ql[kk][3], b0, b1);
                    mma_f16(sc[j], qh[kk][0], qh[kk][1], qh[kk][2], qh[kk][3], c0, c1);
                }
            }
        }

        float m0 = rmax0, m1 = rmax1;
#pragma unroll
        for (int j = 0; j < 8; j++) {
            m0 = fmaxf(m0, fmaxf(sc[j][0], sc[j][1]));
            m1 = fmaxf(m1, fmaxf(sc[j][2], sc[j][3]));
        }
        m0 = fmaxf(m0, __shfl_xor_sync(0xffffffffu, m0, 1));
        m0 = fmaxf(m0, __shfl_xor_sync(0xffffffffu, m0, 2));
        m1 = fmaxf(m1, __shfl_xor_sync(0xffffffffu, m1, 1));
        m1 = fmaxf(m1, __shfl_xor_sync(0xffffffffu, m1, 2));

        bool nm = __any_sync(0xffffffffu, (m0 > rmax0) || (m1 > rmax1));
        if (nm) {
            float alf0 = __expf(rmax0 - m0);
            float alf1 = __expf(rmax1 - m1);
            rsum0 *= alf0; rsum1 *= alf1;
#pragma unroll
            for (int j = 0; j < 16; j++) {
                acc[j][0] *= alf0; acc[j][1] *= alf0;
                acc[j][2] *= alf1; acc[j][3] *= alf1;
            }
            rmax0 = m0; rmax1 = m1;
        }

        uint32_t pp0[8], pp1[8];
        float ps0 = 0.f, ps1 = 0.f;
#pragma unroll
        for (int j = 0; j < 8; j++) {
            float pa = __expf(sc[j][0] - rmax0);
            float pb = __expf(sc[j][1] - rmax0);
            float pc = __expf(sc[j][2] - rmax1);
            float pd = __expf(sc[j][3] - rmax1);
            pp0[j] = cvth(pa, pb);
            pp1[j] = cvth(pc, pd);
            ps0 += pa + pb;
            ps1 += pc + pd;
        }
        ps0 += __shfl_xor_sync(0xffffffffu, ps0, 1);
        ps0 += __shfl_xor_sync(0xffffffffu, ps0, 2);
        ps1 += __shfl_xor_sync(0xffffffffu, ps1, 1);
        ps1 += __shfl_xor_sync(0xffffffffu, ps1, 2);
        rsum0 += ps0;
        rsum1 += ps1;

#pragma unroll
        for (int kk = 0; kk < 4; kk++) {
            uint32_t a0 = pp0[2*kk],   a1 = pp1[2*kk];
            uint32_t a2 = pp0[2*kk+1], a3 = pp1[2*kk+1];
#pragma unroll
            for (int jj = 0; jj < 8; jj++) {
                int nrow = jj*16 + (g>>1)*8 + (lane&7);
                int kc   = kk*8 + (g&1)*4;
                uint32_t b[4];
                ldsm4(b[0], b[1], b[2], b[3], &VT[nrow*36 + kc]);
                mma_f16(acc[2*jj],   a0, a1, a2, a3, b[0], b[1]);
                mma_f16(acc[2*jj+1], a0, a1, a2, a3, b[2], b[3]);
            }
        }
        __syncthreads();
    }

    {
        float inv0 = 1.0f / rsum0;
        float inv1 = 1.0f / rsum1;
        int gr0 = qbase + wbase + (lane >> 2);
        int gr1 = gr0 + 8;
#pragma unroll
        for (int j = 0; j < 16; j++) {
            int col = j*8 + 2*(lane & 3);
            uint32_t w0 = cvth(acc[j][0]*inv0, acc[j][1]*inv0);
            uint32_t w1 = cvth(acc[j][2]*inv1, acc[j][3]*inv1);
            if (col < 32) {
                d_outv16[gr0*128 + ((hoff + col) >> 1)] = w0;
                d_outv16[gr1*128 + ((hoff + col) >> 1)] = w1;
            } else {
                int iv = (col - 32) >> 5, dc = (col - 32) & 31;
                d_outg16[(gr0*NV + iv)*128 + ((hoff + dc) >> 1)] = w0;
                d_outg16[(gr1*NV + iv)*128 + ((hoff + dc) >> 1)] = w1;
            }
        }
    }
}

// ---------------- equ_out = equ@Wc_gd + outg@Wc_og  ([NR,16]) ------------------
__global__ __launch_bounds__(256)
void gdec2_kernel(const float* __restrict__ equ, float* __restrict__ out)
{
    __shared__ float swc[256][16];     // Wc_og
    __shared__ uint32_t so[16][128];   // outg fp16 tile
    __shared__ float se2[16][16];      // equ tile
    __shared__ float swd[256];         // Wc_gd
    int rbase = blockIdx.x * 16;
    int t = threadIdx.x;
#pragma unroll
    for (int l = 0; l < 16; l++) {
        int idx = t + l*256;
        swc[idx >> 4][idx & 15] = d_wc_og[idx];
    }
#pragma unroll
    for (int l = 0; l < 8; l++) {
        int idx = t + l*256;
        so[idx >> 7][idx & 127] = d_outg16[(rbase + (idx >> 7))*128 + (idx & 127)];
    }
    swd[t] = d_wc_gd[t];
    se2[t >> 4][t & 15] = equ[rbase*16 + t];
    __syncthreads();
    int lr = t >> 4, c = t & 15;
    float a0 = 0.f, a1 = 0.f, a2 = 0.f, a3 = 0.f;
#pragma unroll 8
    for (int k2 = 0; k2 < 128; k2 += 2) {
        float2 f0 = __half22float2(*(__half2*)&so[lr][k2]);
        float2 f1 = __half22float2(*(__half2*)&so[lr][k2+1]);
        a0 += f0.x * swc[2*k2][c];
        a1 += f0.y * swc[2*k2+1][c];
        a2 += f1.x * swc[2*k2+2][c];
        a3 += f1.y * swc[2*k2+3][c];
    }
    float ae = 0.f;
#pragma unroll
    for (int m = 0; m < 16; m++) ae += se2[lr][m] * swd[m*16 + c];
    out[(rbase + lr)*16 + c] = ((a0 + a1) + (a2 + a3)) + ae;
}

// ------------------------------------------------------------------------------
extern "C" void kernel_launch(void* const* d_in, const int* in_sizes, int n_in,
                              void* d_out, int out_size)
{
    const float* equ    = (const float*)d_in[0];
    const float* h      = (const float*)d_in[1];
    const float* W_equ  = (const float*)d_in[4];
    const float* W_gproj= (const float*)d_in[5];
    const float* W_vg   = (const float*)d_in[6];
    const float* W_g1   = (const float*)d_in[7];
    const float* b_g1   = (const float*)d_in[8];
    const float* W_g2   = (const float*)d_in[9];
    const float* b_g2   = (const float*)d_in[10];
    const float* W_q    = (const float*)d_in[11];
    const float* b_q    = (const float*)d_in[12];
    const float* W_k    = (const float*)d_in[13];
    const float* b_k    = (const float*)d_in[14];
    const float* W_v    = (const float*)d_in[15];
    const float* b_v    = (const float*)d_in[16];
    const float* W_ng   = (const float*)d_in[17];
    const float* b_ng   = (const float*)d_in[18];
    const float* W_gout = (const float*)d_in[19];
    const float* W_gdec = (const float*)d_in[20];
    const float* W_hdec = (const float*)d_in[21];
    const float* b_hdec = (const float*)d_in[22];
    float* out = (float*)d_out;

#define SYM(p, s) void* p; cudaGetSymbolAddress(&p, s)
    SYM(p_gsh, d_gsh);   SYM(p_hsrc, d_hsrc);
    SYM(p_h2h, d_h2h);   SYM(p_h2l, d_h2l);
    SYM(p_gramh, d_gramh);
    SYM(p_t1h, d_t1h);
    SYM(p_qh, d_qh);     SYM(p_ql, d_ql);
    SYM(p_kh, d_kh);     SYM(p_kl, d_kl);
    SYM(p_v16, d_v16);   SYM(p_vg16, d_vg16);
    SYM(p_outv16, d_outv16); SYM(p_outg16, d_outg16);
    SYM(p_hnew16, d_hnew16);
    SYM(p_wg1h, d_wg1h);
    SYM(p_wg2h, d_wg2h);
    SYM(p_wqh, d_wqh);   SYM(p_wql, d_wql);
    SYM(p_wkh, d_wkh);   SYM(p_wkl, d_wkl);
    SYM(p_wvh, d_wvh);   SYM(p_wvgh, d_wvgh);
    SYM(p_wngh, d_wngh);
    SYM(p_whdech, d_whdech);
#undef SYM

    // 0) weight pre-pack + combined small weights
    WArgs wa;
    wa.e[0] = { W_g1,  (uint32_t*)p_wg1h,  nullptr,            1024, 512, 0, 0   };  // 256
    wa.e[1] = { W_g2,  (uint32_t*)p_wg2h,  nullptr,            512,  256, 0, 256 };  // 64
    wa.e[2] = { W_q,   (uint32_t*)p_wqh,   (uint32_t*)p_wql,   512,  256, 1, 320 };  // 64
    wa.e[3] = { W_k,   (uint32_t*)p_wkh,   (uint32_t*)p_wkl,   512,  256, 1, 384 };  // 64
    wa.e[4] = { W_v,   (uint32_t*)p_wvh,   nullptr,            512,  256, 0, 448 };  // 64
    wa.e[5] = { W_vg,  (uint32_t*)p_wvgh,  nullptr,            256,  256, 0, 512 };  // 32
    wa.e[6] = { W_ng,  (uint32_t*)p_wngh,  nullptr,            256,  256, 0, 544 };  // 32
    wa.e[7] = { W_hdec,(uint32_t*)p_whdech,nullptr,            256,  256, 0, 576 };  // 32
    packall_kernel<<<608, 256>>>(wa);
    combw_kernel<<<18, 256>>>(W_equ, W_gproj, W_gdec, W_gout);

    // 1) prep
    gsrc_kernel<<<NR, 256>>>(equ, W_equ);
    hsrc_kernel<<<NN, 256>>>(h);
    gram_fused_kernel<<<NN/8, 256>>>(equ);

    // 2) MLP on gram (single fp16; g2 emits hi/lo for q/k)
    gemm16p<true, true, false, false, 1><<<dim3(8, 32), 256>>>(
        (uint32_t*)p_gramh, nullptr, (uint32_t*)p_wg1h, nullptr,
        b_g1, nullptr, nullptr, (uint32_t*)p_t1h, nullptr, 1024, 0, 256, 1.f);
    gemm16p<false, true, false, false, 2><<<dim3(4, 32), 256>>>(
        (uint32_t*)p_t1h, nullptr, (uint32_t*)p_wg2h, nullptr,
        b_g2, nullptr, nullptr, (uint32_t*)p_h2h, (uint32_t*)p_h2l, 512, 0, 256, 1.f);

    // 3) q,k (X2 -> packed hi/lo), v,vg (single -> fp16)
    gemm16p<false, true, false, true, 2><<<dim3(4, 32), 256>>>(
        (uint32_t*)p_h2h, (uint32_t*)p_h2l, (uint32_t*)p_wqh, (uint32_t*)p_wql,
        b_q, nullptr, nullptr, (uint32_t*)p_qh, (uint32_t*)p_ql, 512, 0, 128, SCALING);
    gemm16p<false, true, false, true, 2><<<dim3(4, 32), 256>>>(
        (uint32_t*)p_h2h, (uint32_t*)p_h2l, (uint32_t*)p_wkh, (uint32_t*)p_wkl,
        b_k, nullptr, nullptr, (uint32_t*)p_kh, (uint32_t*)p_kl, 512, 0, 128, 1.f);
    gemm16p<false, true, false, false, 1><<<dim3(4, 32), 256>>>(
        (uint32_t*)p_h2h, nullptr, (uint32_t*)p_wvh, nullptr,
        b_v, nullptr, nullptr, (uint32_t*)p_v16, nullptr, 512, 0, 128, 1.f);
    gemm16p<false, false, false, false, 1><<<dim3(4, 96), 256>>>(
        (uint32_t*)p_gsh, nullptr, (uint32_t*)p_wvgh, nullptr,
        nullptr, nullptr, nullptr, (uint32_t*)p_vg16, nullptr, 256, 0, 128, 1.f);

    // 3b) combined V transpose (tiled, coalesced)
    packv_kernel<<<HH*256, 256>>>();

    // 4) register-resident fp16 flash attention (cp.async 2-stage, single wave)
    cudaFuncSetAttribute(attn_reg_kernel, cudaFuncAttributeMaxDynamicSharedMemorySize,
                         AT2_SMEM_BYTES);
    attn_reg_kernel<<<dim3(NN/ATQ, HH), 128, AT2_SMEM_BYTES>>>();

    // 5) h path
    gemm16p<false, true, true, false, 1><<<dim3(4, 32), 256>>>(
        (uint32_t*)p_outv16, nullptr, (uint32_t*)p_wngh, nullptr,
        b_ng, (const float*)p_hsrc, nullptr, (uint32_t*)p_hnew16, nullptr, 256, 256, 128, 1.f);
    gemm16p<false, true, false, false, 0><<<dim3(4, 32), 256>>>(
        (uint32_t*)p_hnew16, nullptr, (uint32_t*)p_whdech, nullptr,
        b_hdec, nullptr, out + NR*MM, nullptr, nullptr, 256, 0, 256, 1.f);

    // 6) g path: equ_out directly from equ + outg (combined weights)
    gdec2_kernel<<<NR/16, 256>>>(equ, out);
}